// round 9
// baseline (speedup 1.0000x reference)
#include <cuda_runtime.h>
#include <stdint.h>

constexpr int THREADS = 128;
constexpr float HSTEP  = 0.05f;     // 0.5 * dt_eff
constexpr float DT_EFF = 0.1f;
constexpr float CMU_H  = 0.00125f;  // 0.5 * h * FRICTION_SCALE
constexpr float TWO_PI     = 6.2831853071795864769f;
constexpr float INV_TWO_PI = 0.15915494309189533577f;

// dynamic smem layout (element counts)
constexpr int N_WF = 8 * 32 * 5;          // uint4
constexpr int N_U  = 32 * 9;              // uint4
constexpr int N_W  = 32 * 9;              // uint4
constexpr int SMEM_BYTES = (N_WF + N_U + N_W) * 16 + 32 * 4 + 128 * 34 * 4 * 2;

// ---------------- helpers ----------------
__device__ __forceinline__ uint32_t bf2(float lo, float hi){
    uint32_t r; asm("cvt.rn.bf16x2.f32 %0, %1, %2;" : "=r"(r) : "f"(hi), "f"(lo)); return r;
}
__device__ __forceinline__ void split2(float x0, float x1, uint32_t& hi, uint32_t& lo){
    hi = bf2(x0, x1);
    float h0 = __uint_as_float(hi << 16);
    float h1 = __uint_as_float(hi & 0xFFFF0000u);
    lo = bf2(x0 - h0, x1 - h1);
}
__device__ __forceinline__ uint32_t pkh(float lo, float hi){
    uint32_t r; asm("cvt.rn.f16x2.f32 %0, %1, %2;" : "=r"(r) : "f"(hi), "f"(lo)); return r;
}
__device__ __forceinline__ uint32_t hadd2(uint32_t a, uint32_t b){
    uint32_t r; asm("add.rn.f16x2 %0, %1, %2;" : "=r"(r) : "r"(a), "r"(b)); return r;
}
__device__ __forceinline__ uint32_t hmul2(uint32_t a, uint32_t b){
    uint32_t r; asm("mul.rn.f16x2 %0, %1, %2;" : "=r"(r) : "r"(a), "r"(b)); return r;
}
__device__ __forceinline__ uint32_t hfma2(uint32_t a, uint32_t b, uint32_t c){
    uint32_t r; asm("fma.rn.f16x2 %0, %1, %2, %3;" : "=r"(r) : "r"(a), "r"(b), "r"(c)); return r;
}
__device__ __forceinline__ uint32_t htanh2(uint32_t a){
    uint32_t r; asm("tanh.approx.f16x2 %0, %1;" : "=r"(r) : "r"(a)); return r;
}
__device__ __forceinline__ uint32_t hneg2(uint32_t a){
    uint32_t r; asm("neg.f16x2 %0, %1;" : "=r"(r) : "r"(a)); return r;
}
__device__ __forceinline__ float2 h2f2(uint32_t h){
    float2 r;
    asm("{ .reg .f16 lo, hi; mov.b32 {lo, hi}, %2; cvt.f32.f16 %0, lo; cvt.f32.f16 %1, hi; }"
        : "=f"(r.x), "=f"(r.y) : "r"(h));
    return r;
}
// bf16 x bf16 -> f32 accum
__device__ __forceinline__ void mma(float* c, uint32_t a0, uint32_t a1, uint32_t a2, uint32_t a3,
                                    uint32_t b0, uint32_t b1){
    asm("mma.sync.aligned.m16n8k16.row.col.f32.bf16.bf16.f32 "
        "{%0,%1,%2,%3}, {%4,%5,%6,%7}, {%8,%9}, {%0,%1,%2,%3};"
        : "+f"(c[0]), "+f"(c[1]), "+f"(c[2]), "+f"(c[3])
        : "r"(a0), "r"(a1), "r"(a2), "r"(a3), "r"(b0), "r"(b1));
}
// f16 x f16 -> f16 accum (2x rate, 2-reg C)
__device__ __forceinline__ void mmah(uint32_t* c, uint32_t a0, uint32_t a1, uint32_t a2, uint32_t a3,
                                     uint32_t b0, uint32_t b1){
    asm("mma.sync.aligned.m16n8k16.row.col.f16.f16.f16.f16 "
        "{%0,%1}, {%2,%3,%4,%5}, {%6,%7}, {%0,%1};"
        : "+r"(c[0]), "+r"(c[1])
        : "r"(a0), "r"(a1), "r"(a2), "r"(a3), "r"(b0), "r"(b1));
}

// =====================================================================
// Warp owns 16 rows, full 64 cols. Thread (g=lane>>2, m=lane&3) owns rows
// {g, g+8}, cols 8s+2m+e; state idx = rr*16 + 2s + e. Matches mma A/C
// fragment layouts; main loop is barrier-free. x and h*force live in SMEM
// (stride-34 thread-private rows -> conflict-free 64-bit LDS/STS).
// Gate and g1 are DE-FUSED so gc and aH/aM/aL accumulators are never
// co-live -> peak register pressure fits 3 CTAs/SM without spilling.
// =====================================================================
__global__ void __launch_bounds__(THREADS, 3)
leapfrog_r9_kernel(const float* __restrict__ x_in, const float* __restrict__ v_in,
                   const float* __restrict__ f_in, const float* __restrict__ U_in,
                   const float* __restrict__ W_in, const float* __restrict__ Wf_in,
                   const float* __restrict__ bf_in, const int* __restrict__ steps_ptr,
                   float* __restrict__ out, int Btot)
{
    extern __shared__ char smraw[];
    uint4*    sWf  = (uint4*)smraw;            // gate B-frags f16 [kt][lane][4j + pad]
    uint4*    sU   = sWf + N_WF;               // U frags [lane][2*kt + (0:hi,1:lo)]
    uint4*    sW   = sU + N_U;                 // W frags [lane][2*j  + (0:hi,1:lo)]
    uint32_t* sB16 = (uint32_t*)(sW + N_W);    // bias f16x2 [nt*4+m]
    float*    sHF  = (float*)(sB16 + 32);      // h*force, stride 34
    float*    sX   = sHF + 128 * 34;           // x state, stride 34

    const int tid = threadIdx.x, wid = tid >> 5, lane = tid & 31;
    const int g = lane >> 2, m = lane & 3;
    const int r0 = blockIdx.x * 64 + wid * 16 + g;
    float* myX  = sX  + tid * 34;
    float* myHF = sHF + tid * 34;

    // ---- gate B-frag table (f16): kt = wid, wid+4 ----
    #pragma unroll
    for (int t = 0; t < 2; t++) {
        int kt = wid + 4 * t;
        #pragma unroll
        for (int j = 0; j < 4; j++) {
            const float* w0 = Wf_in + (8 * (2 * j)     + g) * 128 + 16 * kt;
            const float* w1 = Wf_in + (8 * (2 * j + 1) + g) * 128 + 16 * kt;
            uint4 q;
            q.x = pkh(w0[2 * m],     w0[2 * m + 1]);
            q.y = pkh(w0[8 + 2 * m], w0[9 + 2 * m]);
            q.z = pkh(w1[2 * m],     w1[2 * m + 1]);
            q.w = pkh(w1[8 + 2 * m], w1[9 + 2 * m]);
            sWf[(kt * 32 + lane) * 5 + j] = q;
        }
    }
    // ---- U frags (hi+lo) ----
    if (wid == 0) {
        #pragma unroll
        for (int kt = 0; kt < 4; kt++) {
            uint32_t hi[2][2], lo[2][2];
            #pragma unroll
            for (int nt = 0; nt < 2; nt++) {
                const float* up = U_in + (8 * nt + g) * 64 + 16 * kt;
                split2(up[2 * m],     up[2 * m + 1], hi[nt][0], lo[nt][0]);
                split2(up[8 + 2 * m], up[9 + 2 * m], hi[nt][1], lo[nt][1]);
            }
            sU[lane * 9 + 2 * kt]     = make_uint4(hi[0][0], hi[0][1], hi[1][0], hi[1][1]);
            sU[lane * 9 + 2 * kt + 1] = make_uint4(lo[0][0], lo[0][1], lo[1][0], lo[1][1]);
        }
    }
    // ---- W frags (hi+lo) ----
    if (wid == 1) {
        #pragma unroll
        for (int j = 0; j < 4; j++) {
            uint32_t hi[2][2], lo[2][2];
            #pragma unroll
            for (int u = 0; u < 2; u++) {
                int n = 8 * (2 * j + u) + g;
                split2(W_in[(2 * m) * 64 + n],     W_in[(2 * m + 1) * 64 + n], hi[u][0], lo[u][0]);
                split2(W_in[(2 * m + 8) * 64 + n], W_in[(2 * m + 9) * 64 + n], hi[u][1], lo[u][1]);
            }
            sW[lane * 9 + 2 * j]     = make_uint4(hi[0][0], hi[0][1], hi[1][0], hi[1][1]);
            sW[lane * 9 + 2 * j + 1] = make_uint4(lo[0][0], lo[0][1], lo[1][0], lo[1][1]);
        }
    }
    // ---- bias f16x2 table ----
    if (wid == 2) {
        int nt = lane >> 2, mm = lane & 3;
        sB16[lane] = pkh(bf_in[8 * nt + 2 * mm], bf_in[8 * nt + 2 * mm + 1]);
    }

    // ---- state: v to regs; x and h*force to SMEM ----
    float vr[32];
    uint32_t zr[16];   // packed f16x2: w = z^2 - z  (rden = 1 + w)
    #pragma unroll
    for (int rr = 0; rr < 2; rr++) {
        const size_t base = (size_t)(r0 + 8 * rr) * 64 + 2 * m;
        #pragma unroll
        for (int s = 0; s < 8; s++) {
            float2 t;
            t = *(const float2*)(x_in + base + 8 * s);
            myX[rr * 16 + 2 * s]     = t.x;
            myX[rr * 16 + 2 * s + 1] = t.y;
            t = *(const float2*)(v_in + base + 8 * s);
            vr[rr * 16 + 2 * s] = t.x; vr[rr * 16 + 2 * s + 1] = t.y;
            t = *(const float2*)(f_in + base + 8 * s);
            myHF[rr * 16 + 2 * s]     = HSTEP * t.x;
            myHF[rr * 16 + 2 * s + 1] = HSTEP * t.y;
        }
    }
    __syncthreads();   // only barrier; loop is barrier-free

    const uint32_t H05 = pkh(0.5f, 0.5f);
    const uint32_t CH2 = pkh(CMU_H, CMU_H);
    float aC[2][4];

    // ---- g1: a = v.U^T with 3-way accumulators (standalone) ----
    auto g1 = [&](){
        float aH[2][4], aM[2][4], aL[2][4];
        #pragma unroll
        for (int nt = 0; nt < 2; nt++)
            #pragma unroll
            for (int k = 0; k < 4; k++) { aH[nt][k] = 0.f; aM[nt][k] = 0.f; aL[nt][k] = 0.f; }
        #pragma unroll
        for (int kt = 0; kt < 4; kt++) {
            uint32_t ah0, ah1, ah2, ah3, al0, al1, al2, al3;
            split2(vr[4 * kt],      vr[4 * kt + 1],  ah0, al0);
            split2(vr[16 + 4 * kt], vr[17 + 4 * kt], ah1, al1);
            split2(vr[4 * kt + 2],  vr[4 * kt + 3],  ah2, al2);
            split2(vr[18 + 4 * kt], vr[19 + 4 * kt], ah3, al3);
            uint4 qh = sU[lane * 9 + 2 * kt];
            uint4 ql = sU[lane * 9 + 2 * kt + 1];
            mma(aH[0], ah0, ah1, ah2, ah3, qh.x, qh.y);
            mma(aH[1], ah0, ah1, ah2, ah3, qh.z, qh.w);
            mma(aM[0], ah0, ah1, ah2, ah3, ql.x, ql.y);
            mma(aM[1], ah0, ah1, ah2, ah3, ql.z, ql.w);
            mma(aL[0], al0, al1, al2, al3, qh.x, qh.y);
            mma(aL[1], al0, al1, al2, al3, qh.z, qh.w);
        }
        #pragma unroll
        for (int nt = 0; nt < 2; nt++)
            #pragma unroll
            for (int k = 0; k < 4; k++) aC[nt][k] = aH[nt][k] + aM[nt][k] + aL[nt][k];
    };

    // ---- gate: f16 GEMM on (sin x, cos x) -> zr (standalone) ----
    auto gate = [&](){
        uint32_t gc[8][2];
        #pragma unroll
        for (int nt = 0; nt < 8; nt++) { gc[nt][0] = 0u; gc[nt][1] = 0u; }
        #pragma unroll
        for (int kt = 0; kt < 4; kt++) {
            float s0, c0, s1, c1;
            uint32_t a0, a1, a2, a3, c0p, c1p, c2p, c3p;
            float2 xa = *(const float2*)(myX + 4 * kt);
            float2 xb = *(const float2*)(myX + 16 + 4 * kt);
            float2 xc = *(const float2*)(myX + 4 * kt + 2);
            float2 xd = *(const float2*)(myX + 18 + 4 * kt);
            __sincosf(xa.x, &s0, &c0); __sincosf(xa.y, &s1, &c1);
            a0 = pkh(s0, s1); c0p = pkh(c0, c1);
            __sincosf(xb.x, &s0, &c0); __sincosf(xb.y, &s1, &c1);
            a1 = pkh(s0, s1); c1p = pkh(c0, c1);
            __sincosf(xc.x, &s0, &c0); __sincosf(xc.y, &s1, &c1);
            a2 = pkh(s0, s1); c2p = pkh(c0, c1);
            __sincosf(xd.x, &s0, &c0); __sincosf(xd.y, &s1, &c1);
            a3 = pkh(s0, s1); c3p = pkh(c0, c1);
            #pragma unroll
            for (int j = 0; j < 4; j++) {
                uint4 qs = sWf[(kt * 32 + lane) * 5 + j];
                mmah(gc[2 * j],     a0, a1, a2, a3, qs.x, qs.y);
                mmah(gc[2 * j + 1], a0, a1, a2, a3, qs.z, qs.w);
                uint4 qc = sWf[((kt + 4) * 32 + lane) * 5 + j];
                mmah(gc[2 * j],     c0p, c1p, c2p, c3p, qc.x, qc.y);
                mmah(gc[2 * j + 1], c0p, c1p, c2p, c3p, qc.z, qc.w);
            }
        }
        #pragma unroll
        for (int nt = 0; nt < 8; nt++) {
            uint32_t b2 = sB16[nt * 4 + m];
            #pragma unroll
            for (int rr = 0; rr < 2; rr++) {
                uint32_t gb = hadd2(gc[nt][rr], b2);
                uint32_t th = htanh2(hmul2(gb, H05));
                uint32_t z  = hfma2(th, CH2, CH2);
                zr[2 * nt + rr] = hfma2(z, z, hneg2(z));   // z^2 - z
            }
        }
    };

    // ---- g2 + state update, fused per n-tile ----
    auto g2half = [&](bool first){
        uint32_t h0, h1, h2, h3, l0, l1, l2, l3;
        split2(aC[0][0] * aC[0][0], aC[0][1] * aC[0][1], h0, l0);
        split2(aC[0][2] * aC[0][2], aC[0][3] * aC[0][3], h1, l1);
        split2(aC[1][0] * aC[1][0], aC[1][1] * aC[1][1], h2, l2);
        split2(aC[1][2] * aC[1][2], aC[1][3] * aC[1][3], h3, l3);
        #pragma unroll
        for (int j = 0; j < 4; j++) {
            uint4 qh = sW[lane * 9 + 2 * j];
            uint4 ql = sW[lane * 9 + 2 * j + 1];
            #pragma unroll
            for (int u = 0; u < 2; u++) {
                int nt = 2 * j + u;
                uint32_t bh0 = u ? qh.z : qh.x, bh1 = u ? qh.w : qh.y;
                uint32_t bl0 = u ? ql.z : ql.x, bl1 = u ? ql.w : ql.y;
                float gm[4] = {0.f, 0.f, 0.f, 0.f};
                mma(gm, h0, h1, h2, h3, bh0, bh1);
                mma(gm, h0, h1, h2, h3, bl0, bl1);
                mma(gm, l0, l1, l2, l3, bh0, bh1);
                float2 w0 = h2f2(zr[2 * nt]);
                float2 w1 = h2f2(zr[2 * nt + 1]);
                float2 hf0 = *(const float2*)(myHF + 2 * nt);
                float2 hf1 = *(const float2*)(myHF + 16 + 2 * nt);
                int i0 = 2 * nt, i1 = 2 * nt + 1, i2 = 16 + 2 * nt, i3 = 17 + 2 * nt;
                float t0 = fmaf(-HSTEP, gm[0], vr[i0] + hf0.x);
                float t1 = fmaf(-HSTEP, gm[1], vr[i1] + hf0.y);
                float t2 = fmaf(-HSTEP, gm[2], vr[i2] + hf1.x);
                float t3 = fmaf(-HSTEP, gm[3], vr[i3] + hf1.y);
                vr[i0] = fmaf(t0, w0.x, t0);
                vr[i1] = fmaf(t1, w0.y, t1);
                vr[i2] = fmaf(t2, w1.x, t2);
                vr[i3] = fmaf(t3, w1.y, t3);
                if (first) {
                    float2 xv0 = *(const float2*)(myX + 2 * nt);
                    float2 xv1 = *(const float2*)(myX + 16 + 2 * nt);
                    xv0.x = fmaf(DT_EFF, vr[i0], xv0.x);
                    xv0.y = fmaf(DT_EFF, vr[i1], xv0.y);
                    xv1.x = fmaf(DT_EFF, vr[i2], xv1.x);
                    xv1.y = fmaf(DT_EFF, vr[i3], xv1.y);
                    *(float2*)(myX + 2 * nt) = xv0;
                    *(float2*)(myX + 16 + 2 * nt) = xv1;
                }
            }
        }
    };

    // ---- initial friction at x0 ----
    gate();

    // ---- main loop (barrier-free) ----
    const int steps = steps_ptr[0];
    for (int s = 0; s < steps; s++) {
        g1();                 // a(v)
        g2half(true);         // v_half, x update  (rden from old x)
        gate();               // mu(x_new)
        g1();                 // a(v_half)
        g2half(false);        // final v
    }

    // ---- output: wrap x, write x then v ----
    #pragma unroll
    for (int rr = 0; rr < 2; rr++) {
        const size_t base = (size_t)(r0 + 8 * rr) * 64 + 2 * m;
        #pragma unroll
        for (int s = 0; s < 8; s++) {
            float X0 = myX[rr * 16 + 2 * s], X1 = myX[rr * 16 + 2 * s + 1];
            float2 qx;
            qx.x = fmaf(-TWO_PI, rintf(X0 * INV_TWO_PI), X0);
            qx.y = fmaf(-TWO_PI, rintf(X1 * INV_TWO_PI), X1);
            *(float2*)(out + base + 8 * s) = qx;
            float2 qv = make_float2(vr[rr * 16 + 2 * s], vr[rr * 16 + 2 * s + 1]);
            *(float2*)(out + (size_t)Btot * 64 + base + 8 * s) = qv;
        }
    }
}

extern "C" void kernel_launch(void* const* d_in, const int* in_sizes, int n_in,
                              void* d_out, int out_size)
{
    const float* x  = (const float*)d_in[0];
    const float* v  = (const float*)d_in[1];
    const float* f  = (const float*)d_in[2];
    const float* U  = (const float*)d_in[3];
    const float* W  = (const float*)d_in[4];
    const float* Wf = (const float*)d_in[5];
    const float* bf = (const float*)d_in[6];
    const int* steps = (const int*)d_in[7];

    float* out = (float*)d_out;
    const int Btot = in_sizes[0] / 64;     // 262144
    const int blocks = Btot / 64;          // 4096

    cudaFuncSetAttribute(leapfrog_r9_kernel,
                         cudaFuncAttributeMaxDynamicSharedMemorySize, SMEM_BYTES);
    leapfrog_r9_kernel<<<blocks, THREADS, SMEM_BYTES>>>(x, v, f, U, W, Wf, bf, steps, out, Btot);
}

// round 10
// speedup vs baseline: 1.0124x; 1.0124x over previous
#include <cuda_runtime.h>
#include <stdint.h>

constexpr int THREADS = 128;
constexpr float HSTEP  = 0.05f;     // 0.5 * dt_eff
constexpr float DT_EFF = 0.1f;
constexpr float CMU_H  = 0.00125f;  // 0.5 * h * FRICTION_SCALE
constexpr float TWO_PI     = 6.2831853071795864769f;
constexpr float INV_TWO_PI = 0.15915494309189533577f;

// ---------------- helpers ----------------
__device__ __forceinline__ uint32_t bf2(float lo, float hi){
    uint32_t r; asm("cvt.rn.bf16x2.f32 %0, %1, %2;" : "=r"(r) : "f"(hi), "f"(lo)); return r;
}
__device__ __forceinline__ void split2(float x0, float x1, uint32_t& hi, uint32_t& lo){
    hi = bf2(x0, x1);
    float h0 = __uint_as_float(hi << 16);
    float h1 = __uint_as_float(hi & 0xFFFF0000u);
    lo = bf2(x0 - h0, x1 - h1);
}
__device__ __forceinline__ uint32_t pkh(float lo, float hi){
    uint32_t r; asm("cvt.rn.f16x2.f32 %0, %1, %2;" : "=r"(r) : "f"(hi), "f"(lo)); return r;
}
__device__ __forceinline__ uint32_t hadd2(uint32_t a, uint32_t b){
    uint32_t r; asm("add.rn.f16x2 %0, %1, %2;" : "=r"(r) : "r"(a), "r"(b)); return r;
}
__device__ __forceinline__ uint32_t hmul2(uint32_t a, uint32_t b){
    uint32_t r; asm("mul.rn.f16x2 %0, %1, %2;" : "=r"(r) : "r"(a), "r"(b)); return r;
}
__device__ __forceinline__ uint32_t hfma2(uint32_t a, uint32_t b, uint32_t c){
    uint32_t r; asm("fma.rn.f16x2 %0, %1, %2, %3;" : "=r"(r) : "r"(a), "r"(b), "r"(c)); return r;
}
__device__ __forceinline__ uint32_t htanh2(uint32_t a){
    uint32_t r; asm("tanh.approx.f16x2 %0, %1;" : "=r"(r) : "r"(a)); return r;
}
__device__ __forceinline__ uint32_t hneg2(uint32_t a){
    uint32_t r; asm("neg.f16x2 %0, %1;" : "=r"(r) : "r"(a)); return r;
}
__device__ __forceinline__ float2 h2f2(uint32_t h){
    float2 r;
    asm("{ .reg .f16 lo, hi; mov.b32 {lo, hi}, %2; cvt.f32.f16 %0, lo; cvt.f32.f16 %1, hi; }"
        : "=f"(r.x), "=f"(r.y) : "r"(h));
    return r;
}
// bf16 x bf16 -> f32 accum
__device__ __forceinline__ void mma(float* c, uint32_t a0, uint32_t a1, uint32_t a2, uint32_t a3,
                                    uint32_t b0, uint32_t b1){
    asm("mma.sync.aligned.m16n8k16.row.col.f32.bf16.bf16.f32 "
        "{%0,%1,%2,%3}, {%4,%5,%6,%7}, {%8,%9}, {%0,%1,%2,%3};"
        : "+f"(c[0]), "+f"(c[1]), "+f"(c[2]), "+f"(c[3])
        : "r"(a0), "r"(a1), "r"(a2), "r"(a3), "r"(b0), "r"(b1));
}
// f16 x f16 -> f16 accum (2x rate, 2-reg C)
__device__ __forceinline__ void mmah(uint32_t* c, uint32_t a0, uint32_t a1, uint32_t a2, uint32_t a3,
                                     uint32_t b0, uint32_t b1){
    asm("mma.sync.aligned.m16n8k16.row.col.f16.f16.f16.f16 "
        "{%0,%1}, {%2,%3,%4,%5}, {%6,%7}, {%0,%1};"
        : "+r"(c[0]), "+r"(c[1])
        : "r"(a0), "r"(a1), "r"(a2), "r"(a3), "r"(b0), "r"(b1));
}

// =====================================================================
// R4 structure (all-register state, 2 CTAs/SM, barrier-free loop) with
// the two work-reducing R6 changes: f16-accum gate MMA + packed f16 rden.
// Warp owns 16 rows; thread (g=lane>>2, m=lane&3) owns rows {g, g+8},
// cols 8s+2m+e; state idx = rr*16 + 2s + e.
// =====================================================================
__global__ void __launch_bounds__(THREADS, 2)
leapfrog_r10_kernel(const float* __restrict__ x_in, const float* __restrict__ v_in,
                    const float* __restrict__ f_in, const float* __restrict__ U_in,
                    const float* __restrict__ W_in, const float* __restrict__ Wf_in,
                    const float* __restrict__ bf_in, const int* __restrict__ steps_ptr,
                    float* __restrict__ out, int Btot)
{
    __shared__ uint4 sWf[8 * 32 * 5];   // gate B-frags f16 [kt][lane][4j + pad]
    __shared__ uint4 sUl[32 * 5];       // U lo-frags [lane][kt + pad]
    __shared__ uint4 sWl[32 * 5];       // W lo-frags [lane][j + pad]
    __shared__ uint32_t sB16[32];       // bias f16x2 [nt*4+m]

    const int tid = threadIdx.x, wid = tid >> 5, lane = tid & 31;
    const int g = lane >> 2, m = lane & 3;
    const int r0 = blockIdx.x * 64 + wid * 16 + g;

    // ---- gate B-frag table (f16): kt = wid, wid+4 ----
    #pragma unroll
    for (int t = 0; t < 2; t++) {
        int kt = wid + 4 * t;
        #pragma unroll
        for (int j = 0; j < 4; j++) {
            const float* w0 = Wf_in + (8 * (2 * j)     + g) * 128 + 16 * kt;
            const float* w1 = Wf_in + (8 * (2 * j + 1) + g) * 128 + 16 * kt;
            uint4 q;
            q.x = pkh(w0[2 * m],     w0[2 * m + 1]);
            q.y = pkh(w0[8 + 2 * m], w0[9 + 2 * m]);
            q.z = pkh(w1[2 * m],     w1[2 * m + 1]);
            q.w = pkh(w1[8 + 2 * m], w1[9 + 2 * m]);
            sWf[(kt * 32 + lane) * 5 + j] = q;
        }
    }

    // ---- U fragments: hi in regs, lo in SMEM ----
    uint32_t Uh[2][4][2];
    {
        uint4 qlo[4];
        #pragma unroll
        for (int kt = 0; kt < 4; kt++) {
            uint32_t lo[2][2];
            #pragma unroll
            for (int nt = 0; nt < 2; nt++) {
                const float* up = U_in + (8 * nt + g) * 64 + 16 * kt;
                split2(up[2 * m],     up[2 * m + 1], Uh[nt][kt][0], lo[nt][0]);
                split2(up[8 + 2 * m], up[9 + 2 * m], Uh[nt][kt][1], lo[nt][1]);
            }
            qlo[kt] = make_uint4(lo[0][0], lo[0][1], lo[1][0], lo[1][1]);
        }
        if (wid == 0) {
            #pragma unroll
            for (int kt = 0; kt < 4; kt++) sUl[lane * 5 + kt] = qlo[kt];
        }
    }

    // ---- W fragments: hi in regs, lo in SMEM ----
    uint32_t Wh[8][2];
    {
        uint4 qlo[4];
        #pragma unroll
        for (int j = 0; j < 4; j++) {
            uint32_t lo[2][2];
            #pragma unroll
            for (int u = 0; u < 2; u++) {
                int nt = 2 * j + u, n = 8 * nt + g;
                split2(W_in[(2 * m) * 64 + n],     W_in[(2 * m + 1) * 64 + n], Wh[nt][0], lo[u][0]);
                split2(W_in[(2 * m + 8) * 64 + n], W_in[(2 * m + 9) * 64 + n], Wh[nt][1], lo[u][1]);
            }
            qlo[j] = make_uint4(lo[0][0], lo[0][1], lo[1][0], lo[1][1]);
        }
        if (wid == 1) {
            #pragma unroll
            for (int j = 0; j < 4; j++) sWl[lane * 5 + j] = qlo[j];
        }
    }
    // ---- bias f16x2 table ----
    if (wid == 2) {
        int nt = lane >> 2, mm = lane & 3;
        sB16[lane] = pkh(bf_in[8 * nt + 2 * mm], bf_in[8 * nt + 2 * mm + 1]);
    }

    // ---- state into registers (hf = h*force) ----
    float xr[32], vr[32], hf[32];
    uint32_t zr[16];   // packed f16x2: w = z^2 - z  (rden = 1 + w)
    #pragma unroll
    for (int rr = 0; rr < 2; rr++) {
        const size_t base = (size_t)(r0 + 8 * rr) * 64 + 2 * m;
        #pragma unroll
        for (int s = 0; s < 8; s++) {
            float2 t;
            t = *(const float2*)(x_in + base + 8 * s); xr[rr * 16 + 2 * s] = t.x; xr[rr * 16 + 2 * s + 1] = t.y;
            t = *(const float2*)(v_in + base + 8 * s); vr[rr * 16 + 2 * s] = t.x; vr[rr * 16 + 2 * s + 1] = t.y;
            t = *(const float2*)(f_in + base + 8 * s);
            hf[rr * 16 + 2 * s]     = HSTEP * t.x;
            hf[rr * 16 + 2 * s + 1] = HSTEP * t.y;
        }
    }
    __syncthreads();   // only barrier; loop below is barrier-free

    const uint32_t H05 = pkh(0.5f, 0.5f);
    const uint32_t CH2 = pkh(CMU_H, CMU_H);
    float aC[2][4];

    // ---- one g1 k-block (3-way accumulators, chain depth 4) ----
    auto g1_block = [&](int kt, float aH[2][4], float aM[2][4], float aL[2][4]){
        uint32_t ah0, ah1, ah2, ah3, al0, al1, al2, al3;
        split2(vr[4 * kt],      vr[4 * kt + 1],  ah0, al0);
        split2(vr[16 + 4 * kt], vr[17 + 4 * kt], ah1, al1);
        split2(vr[4 * kt + 2],  vr[4 * kt + 3],  ah2, al2);
        split2(vr[18 + 4 * kt], vr[19 + 4 * kt], ah3, al3);
        uint4 ql = sUl[lane * 5 + kt];
        mma(aH[0], ah0, ah1, ah2, ah3, Uh[0][kt][0], Uh[0][kt][1]);
        mma(aH[1], ah0, ah1, ah2, ah3, Uh[1][kt][0], Uh[1][kt][1]);
        mma(aM[0], ah0, ah1, ah2, ah3, ql.x, ql.y);
        mma(aM[1], ah0, ah1, ah2, ah3, ql.z, ql.w);
        mma(aL[0], al0, al1, al2, al3, Uh[0][kt][0], Uh[0][kt][1]);
        mma(aL[1], al0, al1, al2, al3, Uh[1][kt][0], Uh[1][kt][1]);
    };

    auto g1 = [&](){
        float aH[2][4], aM[2][4], aL[2][4];
        #pragma unroll
        for (int nt = 0; nt < 2; nt++)
            #pragma unroll
            for (int k = 0; k < 4; k++) { aH[nt][k] = 0.f; aM[nt][k] = 0.f; aL[nt][k] = 0.f; }
        #pragma unroll
        for (int kt = 0; kt < 4; kt++) g1_block(kt, aH, aM, aL);
        #pragma unroll
        for (int nt = 0; nt < 2; nt++)
            #pragma unroll
            for (int k = 0; k < 4; k++) aC[nt][k] = aH[nt][k] + aM[nt][k] + aL[nt][k];
    };

    // ---- fused: f16 gate GEMM (+ optional g1), sin/cos interleaved ----
    auto fused_gate = [&](bool with_g1){
        uint32_t gc[8][2];
        #pragma unroll
        for (int nt = 0; nt < 8; nt++) { gc[nt][0] = 0u; gc[nt][1] = 0u; }
        float aH[2][4], aM[2][4], aL[2][4];
        if (with_g1) {
            #pragma unroll
            for (int nt = 0; nt < 2; nt++)
                #pragma unroll
                for (int k = 0; k < 4; k++) { aH[nt][k] = 0.f; aM[nt][k] = 0.f; aL[nt][k] = 0.f; }
        }
        #pragma unroll
        for (int kt = 0; kt < 4; kt++) {
            float s0, c0, s1, c1;
            uint32_t a0, a1, a2, a3, c0p, c1p, c2p, c3p;
            __sincosf(xr[4 * kt],      &s0, &c0);
            __sincosf(xr[4 * kt + 1],  &s1, &c1);
            a0 = pkh(s0, s1); c0p = pkh(c0, c1);
            __sincosf(xr[16 + 4 * kt], &s0, &c0);
            __sincosf(xr[17 + 4 * kt], &s1, &c1);
            a1 = pkh(s0, s1); c1p = pkh(c0, c1);
            __sincosf(xr[4 * kt + 2],  &s0, &c0);
            __sincosf(xr[4 * kt + 3],  &s1, &c1);
            a2 = pkh(s0, s1); c2p = pkh(c0, c1);
            __sincosf(xr[18 + 4 * kt], &s0, &c0);
            __sincosf(xr[19 + 4 * kt], &s1, &c1);
            a3 = pkh(s0, s1); c3p = pkh(c0, c1);
            #pragma unroll
            for (int j = 0; j < 4; j++) {
                uint4 qs = sWf[(kt * 32 + lane) * 5 + j];
                mmah(gc[2 * j],     a0, a1, a2, a3, qs.x, qs.y);
                mmah(gc[2 * j + 1], a0, a1, a2, a3, qs.z, qs.w);
                uint4 qc = sWf[((kt + 4) * 32 + lane) * 5 + j];
                mmah(gc[2 * j],     c0p, c1p, c2p, c3p, qc.x, qc.y);
                mmah(gc[2 * j + 1], c0p, c1p, c2p, c3p, qc.z, qc.w);
            }
            if (with_g1) g1_block(kt, aH, aM, aL);
        }
        if (with_g1) {
            #pragma unroll
            for (int nt = 0; nt < 2; nt++)
                #pragma unroll
                for (int k = 0; k < 4; k++) aC[nt][k] = aH[nt][k] + aM[nt][k] + aL[nt][k];
        }
        #pragma unroll
        for (int nt = 0; nt < 8; nt++) {
            uint32_t b2 = sB16[nt * 4 + m];
            #pragma unroll
            for (int rr = 0; rr < 2; rr++) {
                uint32_t gb = hadd2(gc[nt][rr], b2);
                uint32_t th = htanh2(hmul2(gb, H05));
                uint32_t z  = hfma2(th, CH2, CH2);
                zr[2 * nt + rr] = hfma2(z, z, hneg2(z));   // z^2 - z
            }
        }
    };

    // ---- g2 + state update, fused per n-tile ----
    auto g2half = [&](bool first){
        uint32_t h0, h1, h2, h3, l0, l1, l2, l3;
        split2(aC[0][0] * aC[0][0], aC[0][1] * aC[0][1], h0, l0);
        split2(aC[0][2] * aC[0][2], aC[0][3] * aC[0][3], h1, l1);
        split2(aC[1][0] * aC[1][0], aC[1][1] * aC[1][1], h2, l2);
        split2(aC[1][2] * aC[1][2], aC[1][3] * aC[1][3], h3, l3);
        #pragma unroll
        for (int j = 0; j < 4; j++) {
            uint4 ql = sWl[lane * 5 + j];
            uint32_t Wlf[2][2] = {{ql.x, ql.y}, {ql.z, ql.w}};
            #pragma unroll
            for (int u = 0; u < 2; u++) {
                int nt = 2 * j + u;
                float gm[4] = {0.f, 0.f, 0.f, 0.f};
                mma(gm, h0, h1, h2, h3, Wh[nt][0], Wh[nt][1]);
                mma(gm, h0, h1, h2, h3, Wlf[u][0], Wlf[u][1]);
                mma(gm, l0, l1, l2, l3, Wh[nt][0], Wh[nt][1]);
                float2 w0 = h2f2(zr[2 * nt]);
                float2 w1 = h2f2(zr[2 * nt + 1]);
                int i0 = 2 * nt, i1 = 2 * nt + 1, i2 = 16 + 2 * nt, i3 = 17 + 2 * nt;
                float t0 = fmaf(-HSTEP, gm[0], vr[i0] + hf[i0]);
                float t1 = fmaf(-HSTEP, gm[1], vr[i1] + hf[i1]);
                float t2 = fmaf(-HSTEP, gm[2], vr[i2] + hf[i2]);
                float t3 = fmaf(-HSTEP, gm[3], vr[i3] + hf[i3]);
                vr[i0] = fmaf(t0, w0.x, t0);
                vr[i1] = fmaf(t1, w0.y, t1);
                vr[i2] = fmaf(t2, w1.x, t2);
                vr[i3] = fmaf(t3, w1.y, t3);
                if (first) {
                    xr[i0] = fmaf(DT_EFF, vr[i0], xr[i0]);
                    xr[i1] = fmaf(DT_EFF, vr[i1], xr[i1]);
                    xr[i2] = fmaf(DT_EFF, vr[i2], xr[i2]);
                    xr[i3] = fmaf(DT_EFF, vr[i3], xr[i3]);
                }
            }
        }
    };

    // ---- initial friction at x0 ----
    fused_gate(false);

    // ---- main loop (barrier-free) ----
    const int steps = steps_ptr[0];
    for (int s = 0; s < steps; s++) {
        g1();                 // a(v)
        g2half(true);         // v_half, x update (rden from old x)
        fused_gate(true);     // mu(x_new) || a(v_half)
        g2half(false);        // final v
    }

    // ---- output: wrap x, write x then v ----
    #pragma unroll
    for (int rr = 0; rr < 2; rr++) {
        const size_t base = (size_t)(r0 + 8 * rr) * 64 + 2 * m;
        #pragma unroll
        for (int s = 0; s < 8; s++) {
            float X0 = xr[rr * 16 + 2 * s], X1 = xr[rr * 16 + 2 * s + 1];
            float2 qx;
            qx.x = fmaf(-TWO_PI, rintf(X0 * INV_TWO_PI), X0);
            qx.y = fmaf(-TWO_PI, rintf(X1 * INV_TWO_PI), X1);
            *(float2*)(out + base + 8 * s) = qx;
            float2 qv = make_float2(vr[rr * 16 + 2 * s], vr[rr * 16 + 2 * s + 1]);
            *(float2*)(out + (size_t)Btot * 64 + base + 8 * s) = qv;
        }
    }
}

extern "C" void kernel_launch(void* const* d_in, const int* in_sizes, int n_in,
                              void* d_out, int out_size)
{
    const float* x  = (const float*)d_in[0];
    const float* v  = (const float*)d_in[1];
    const float* f  = (const float*)d_in[2];
    const float* U  = (const float*)d_in[3];
    const float* W  = (const float*)d_in[4];
    const float* Wf = (const float*)d_in[5];
    const float* bf = (const float*)d_in[6];
    const int* steps = (const int*)d_in[7];

    float* out = (float*)d_out;
    const int Btot = in_sizes[0] / 64;     // 262144
    const int blocks = Btot / 64;          // 4096

    leapfrog_r10_kernel<<<blocks, THREADS>>>(x, v, f, U, W, Wf, bf, steps, out, Btot);
}

// round 11
// speedup vs baseline: 1.0985x; 1.0851x over previous
#include <cuda_runtime.h>
#include <stdint.h>

constexpr int THREADS = 128;
constexpr float HSTEP  = 0.05f;     // 0.5 * dt_eff
constexpr float DT_EFF = 0.1f;
constexpr float CMU_H  = 0.00125f;  // 0.5 * h * FRICTION_SCALE
constexpr float TWO_PI     = 6.2831853071795864769f;
constexpr float INV_TWO_PI = 0.15915494309189533577f;

// ---------------- helpers ----------------
__device__ __forceinline__ uint32_t bf2(float lo, float hi){
    uint32_t r; asm("cvt.rn.bf16x2.f32 %0, %1, %2;" : "=r"(r) : "f"(hi), "f"(lo)); return r;
}
// hi/lo bf16 split: x = hi + lo with |lo| <= 2^-8 |x|, residual err ~2^-17
__device__ __forceinline__ void split2(float x0, float x1, uint32_t& hi, uint32_t& lo){
    hi = bf2(x0, x1);
    float h0 = __uint_as_float(hi << 16);
    float h1 = __uint_as_float(hi & 0xFFFF0000u);
    lo = bf2(x0 - h0, x1 - h1);
}
__device__ __forceinline__ float tanha(float x){
    float y; asm("tanh.approx.f32 %0, %1;" : "=f"(y) : "f"(x)); return y;
}
// rden = 1/(1 + h*mu), h*mu = CMU_H*(1+tanh(g/2));  1/(1+z) ~= 1 - z + z^2
__device__ __forceinline__ float rdenf(float gate){
    float z = CMU_H * (1.0f + tanha(0.5f * gate));
    return fmaf(z, z, 1.0f) - z;
}
// bf16 x bf16 -> f32 accum
__device__ __forceinline__ void mma(float* c, uint32_t a0, uint32_t a1, uint32_t a2, uint32_t a3,
                                    uint32_t b0, uint32_t b1){
    asm("mma.sync.aligned.m16n8k16.row.col.f32.bf16.bf16.f32 "
        "{%0,%1,%2,%3}, {%4,%5,%6,%7}, {%8,%9}, {%0,%1,%2,%3};"
        : "+f"(c[0]), "+f"(c[1]), "+f"(c[2]), "+f"(c[3])
        : "r"(a0), "r"(a1), "r"(a2), "r"(a3), "r"(b0), "r"(b1));
}

// =====================================================================
// R4 basin: warp owns 16 rows, full 64 cols; thread (g=lane>>2, m=lane&3)
// owns rows {g, g+8}, cols 8s+2m+e; state idx = rr*16 + 2s + e.
// All state in registers, 2 CTAs/SM, barrier-free loop.
// R11 chain cuts: fused g2+update (no gamC array), 2-way g2 accumulators,
// interleaved sin/cos gate (no cos stash), state LDGs issued first.
// =====================================================================
__global__ void __launch_bounds__(THREADS, 2)
leapfrog_r11_kernel(const float* __restrict__ x_in, const float* __restrict__ v_in,
                    const float* __restrict__ f_in, const float* __restrict__ U_in,
                    const float* __restrict__ W_in, const float* __restrict__ Wf_in,
                    const float* __restrict__ bf_in, const int* __restrict__ steps_ptr,
                    float* __restrict__ out, int Btot)
{
    __shared__ uint4 sWf[8 * 32 * 5];   // gate B-frags bf16 [kt][lane][4j + pad]
    __shared__ uint4 sUl[32 * 5];       // U lo-frags [lane][kt + pad]
    __shared__ uint4 sWl[32 * 5];       // W lo-frags [lane][j + pad]
    __shared__ float sBias[64];

    const int tid = threadIdx.x, wid = tid >> 5, lane = tid & 31;
    const int g = lane >> 2, m = lane & 3;
    const int r0 = blockIdx.x * 64 + wid * 16 + g;

    // ---- state LDGs first: fill MLP, overlap with weight preprocessing ----
    float xr[32], vr[32], fr[32], rden[32];
    #pragma unroll
    for (int rr = 0; rr < 2; rr++) {
        const size_t base = (size_t)(r0 + 8 * rr) * 64 + 2 * m;
        #pragma unroll
        for (int s = 0; s < 8; s++) {
            float2 t;
            t = *(const float2*)(x_in + base + 8 * s); xr[rr * 16 + 2 * s] = t.x; xr[rr * 16 + 2 * s + 1] = t.y;
            t = *(const float2*)(v_in + base + 8 * s); vr[rr * 16 + 2 * s] = t.x; vr[rr * 16 + 2 * s + 1] = t.y;
            t = *(const float2*)(f_in + base + 8 * s); fr[rr * 16 + 2 * s] = t.x; fr[rr * 16 + 2 * s + 1] = t.y;
        }
    }

    // ---- gate B-fragment table: Wf [64][128], B[n][k] = Wf[n][k] ----
    #pragma unroll
    for (int t = 0; t < 2; t++) {
        int kt = wid + 4 * t;
        #pragma unroll
        for (int j = 0; j < 4; j++) {
            const float* w0 = Wf_in + (8 * (2 * j)     + g) * 128 + 16 * kt;
            const float* w1 = Wf_in + (8 * (2 * j + 1) + g) * 128 + 16 * kt;
            uint4 q;
            q.x = bf2(w0[2 * m],     w0[2 * m + 1]);
            q.y = bf2(w0[8 + 2 * m], w0[9 + 2 * m]);
            q.z = bf2(w1[2 * m],     w1[2 * m + 1]);
            q.w = bf2(w1[8 + 2 * m], w1[9 + 2 * m]);
            sWf[(kt * 32 + lane) * 5 + j] = q;
        }
    }

    // ---- U fragments: hi in regs, lo in SMEM ----
    uint32_t Uh[2][4][2];
    {
        uint4 qlo[4];
        #pragma unroll
        for (int kt = 0; kt < 4; kt++) {
            uint32_t lo[2][2];
            #pragma unroll
            for (int nt = 0; nt < 2; nt++) {
                const float* up = U_in + (8 * nt + g) * 64 + 16 * kt;
                split2(up[2 * m],     up[2 * m + 1], Uh[nt][kt][0], lo[nt][0]);
                split2(up[8 + 2 * m], up[9 + 2 * m], Uh[nt][kt][1], lo[nt][1]);
            }
            qlo[kt] = make_uint4(lo[0][0], lo[0][1], lo[1][0], lo[1][1]);
        }
        if (wid == 0) {
            #pragma unroll
            for (int kt = 0; kt < 4; kt++) sUl[lane * 5 + kt] = qlo[kt];
        }
    }

    // ---- W fragments: hi in regs, lo in SMEM ----
    uint32_t Wh[8][2];
    {
        uint4 qlo[4];
        #pragma unroll
        for (int j = 0; j < 4; j++) {
            uint32_t lo[2][2];
            #pragma unroll
            for (int u = 0; u < 2; u++) {
                int nt = 2 * j + u, n = 8 * nt + g;
                split2(W_in[(2 * m) * 64 + n],     W_in[(2 * m + 1) * 64 + n], Wh[nt][0], lo[u][0]);
                split2(W_in[(2 * m + 8) * 64 + n], W_in[(2 * m + 9) * 64 + n], Wh[nt][1], lo[u][1]);
            }
            qlo[j] = make_uint4(lo[0][0], lo[0][1], lo[1][0], lo[1][1]);
        }
        if (wid == 1) {
            #pragma unroll
            for (int j = 0; j < 4; j++) sWl[lane * 5 + j] = qlo[j];
        }
    }
    if (tid < 64) sBias[tid] = bf_in[tid];

    __syncthreads();   // the only barrier; loop below is barrier-free

    float aC[2][4];

    // ---- one g1 k-block with 3-way accumulators (chain depth 4) ----
    auto g1_block = [&](int kt, float aH[2][4], float aM[2][4], float aL[2][4]){
        uint32_t ah0, ah1, ah2, ah3, al0, al1, al2, al3;
        split2(vr[4 * kt],      vr[4 * kt + 1],  ah0, al0);
        split2(vr[16 + 4 * kt], vr[17 + 4 * kt], ah1, al1);
        split2(vr[4 * kt + 2],  vr[4 * kt + 3],  ah2, al2);
        split2(vr[18 + 4 * kt], vr[19 + 4 * kt], ah3, al3);
        uint4 ql = sUl[lane * 5 + kt];
        mma(aH[0], ah0, ah1, ah2, ah3, Uh[0][kt][0], Uh[0][kt][1]);
        mma(aH[1], ah0, ah1, ah2, ah3, Uh[1][kt][0], Uh[1][kt][1]);
        mma(aM[0], ah0, ah1, ah2, ah3, ql.x, ql.y);
        mma(aM[1], ah0, ah1, ah2, ah3, ql.z, ql.w);
        mma(aL[0], al0, al1, al2, al3, Uh[0][kt][0], Uh[0][kt][1]);
        mma(aL[1], al0, al1, al2, al3, Uh[1][kt][0], Uh[1][kt][1]);
    };

    // ---- standalone g1 ----
    auto g1 = [&](){
        float aH[2][4], aM[2][4], aL[2][4];
        #pragma unroll
        for (int nt = 0; nt < 2; nt++)
            #pragma unroll
            for (int k = 0; k < 4; k++) { aH[nt][k] = 0.f; aM[nt][k] = 0.f; aL[nt][k] = 0.f; }
        #pragma unroll
        for (int kt = 0; kt < 4; kt++) g1_block(kt, aH, aM, aL);
        #pragma unroll
        for (int nt = 0; nt < 2; nt++)
            #pragma unroll
            for (int k = 0; k < 4; k++) aC[nt][k] = aH[nt][k] + aM[nt][k] + aL[nt][k];
    };

    // ---- fused: bf16 gate GEMM (+ optional g1), sin/cos interleaved ----
    auto fused_gate = [&](bool with_g1){
        float gc[8][4];
        #pragma unroll
        for (int nt = 0; nt < 8; nt++)
            #pragma unroll
            for (int k = 0; k < 4; k++) gc[nt][k] = 0.0f;
        float aH[2][4], aM[2][4], aL[2][4];
        if (with_g1) {
            #pragma unroll
            for (int nt = 0; nt < 2; nt++)
                #pragma unroll
                for (int k = 0; k < 4; k++) { aH[nt][k] = 0.f; aM[nt][k] = 0.f; aL[nt][k] = 0.f; }
        }
        #pragma unroll
        for (int kt = 0; kt < 4; kt++) {
            float s0, c0, s1, c1;
            uint32_t a0, a1, a2, a3, c0p, c1p, c2p, c3p;
            __sincosf(xr[4 * kt],      &s0, &c0);
            __sincosf(xr[4 * kt + 1],  &s1, &c1);
            a0 = bf2(s0, s1); c0p = bf2(c0, c1);
            __sincosf(xr[16 + 4 * kt], &s0, &c0);
            __sincosf(xr[17 + 4 * kt], &s1, &c1);
            a1 = bf2(s0, s1); c1p = bf2(c0, c1);
            __sincosf(xr[4 * kt + 2],  &s0, &c0);
            __sincosf(xr[4 * kt + 3],  &s1, &c1);
            a2 = bf2(s0, s1); c2p = bf2(c0, c1);
            __sincosf(xr[18 + 4 * kt], &s0, &c0);
            __sincosf(xr[19 + 4 * kt], &s1, &c1);
            a3 = bf2(s0, s1); c3p = bf2(c0, c1);
            #pragma unroll
            for (int j = 0; j < 4; j++) {
                uint4 qs = sWf[(kt * 32 + lane) * 5 + j];
                mma(gc[2 * j],     a0, a1, a2, a3, qs.x, qs.y);
                mma(gc[2 * j + 1], a0, a1, a2, a3, qs.z, qs.w);
                uint4 qc = sWf[((kt + 4) * 32 + lane) * 5 + j];
                mma(gc[2 * j],     c0p, c1p, c2p, c3p, qc.x, qc.y);
                mma(gc[2 * j + 1], c0p, c1p, c2p, c3p, qc.z, qc.w);
            }
            if (with_g1) g1_block(kt, aH, aM, aL);
        }
        if (with_g1) {
            #pragma unroll
            for (int nt = 0; nt < 2; nt++)
                #pragma unroll
                for (int k = 0; k < 4; k++) aC[nt][k] = aH[nt][k] + aM[nt][k] + aL[nt][k];
        }
        #pragma unroll
        for (int nt = 0; nt < 8; nt++) {
            float2 bb = *(const float2*)(sBias + 8 * nt + 2 * m);
            rden[2 * nt]      = rdenf(gc[nt][0] + bb.x);
            rden[2 * nt + 1]  = rdenf(gc[nt][1] + bb.y);
            rden[16 + 2 * nt] = rdenf(gc[nt][2] + bb.x);
            rden[17 + 2 * nt] = rdenf(gc[nt][3] + bb.y);
        }
    };

    // ---- g2 fused with state update, 2-way accumulators per n-tile ----
    auto g2half = [&](bool first){
        uint32_t h0, h1, h2, h3, l0, l1, l2, l3;
        split2(aC[0][0] * aC[0][0], aC[0][1] * aC[0][1], h0, l0);
        split2(aC[0][2] * aC[0][2], aC[0][3] * aC[0][3], h1, l1);
        split2(aC[1][0] * aC[1][0], aC[1][1] * aC[1][1], h2, l2);
        split2(aC[1][2] * aC[1][2], aC[1][3] * aC[1][3], h3, l3);
        #pragma unroll
        for (int j = 0; j < 4; j++) {
            uint4 ql = sWl[lane * 5 + j];
            uint32_t Wlf[2][2] = {{ql.x, ql.y}, {ql.z, ql.w}};
            #pragma unroll
            for (int u = 0; u < 2; u++) {
                int nt = 2 * j + u;
                float gA[4] = {0.f, 0.f, 0.f, 0.f};   // hh then lo*hi (depth 2)
                float gB[4] = {0.f, 0.f, 0.f, 0.f};   // hi*lo (depth 1, parallel)
                mma(gA, h0, h1, h2, h3, Wh[nt][0], Wh[nt][1]);
                mma(gB, h0, h1, h2, h3, Wlf[u][0], Wlf[u][1]);
                mma(gA, l0, l1, l2, l3, Wh[nt][0], Wh[nt][1]);
                int idx[4] = {2 * nt, 2 * nt + 1, 16 + 2 * nt, 17 + 2 * nt};
                #pragma unroll
                for (int k = 0; k < 4; k++) {
                    int i = idx[k];
                    float gm = gA[k] + gB[k];
                    float vn = (vr[i] + HSTEP * (fr[i] - gm)) * rden[i];
                    vr[i] = vn;
                    if (first) xr[i] = fmaf(DT_EFF, vn, xr[i]);
                }
            }
        }
    };

    // ---- initial friction at x0 ----
    fused_gate(false);

    // ---- main loop (barrier-free) ----
    const int steps = steps_ptr[0];
    for (int s = 0; s < steps; s++) {
        g1();                 // a(v)
        g2half(true);         // v_half, x update (rden = mu at old x)
        fused_gate(true);     // mu(x_new) || a(v_half)
        g2half(false);        // final v of the step
    }

    // ---- output: wrap x, write x then v ----
    #pragma unroll
    for (int rr = 0; rr < 2; rr++) {
        const size_t base = (size_t)(r0 + 8 * rr) * 64 + 2 * m;
        #pragma unroll
        for (int s = 0; s < 8; s++) {
            float X0 = xr[rr * 16 + 2 * s], X1 = xr[rr * 16 + 2 * s + 1];
            float2 qx;
            qx.x = fmaf(-TWO_PI, rintf(X0 * INV_TWO_PI), X0);
            qx.y = fmaf(-TWO_PI, rintf(X1 * INV_TWO_PI), X1);
            *(float2*)(out + base + 8 * s) = qx;
            float2 qv = make_float2(vr[rr * 16 + 2 * s], vr[rr * 16 + 2 * s + 1]);
            *(float2*)(out + (size_t)Btot * 64 + base + 8 * s) = qv;
        }
    }
}

extern "C" void kernel_launch(void* const* d_in, const int* in_sizes, int n_in,
                              void* d_out, int out_size)
{
    const float* x  = (const float*)d_in[0];
    const float* v  = (const float*)d_in[1];
    const float* f  = (const float*)d_in[2];
    const float* U  = (const float*)d_in[3];
    const float* W  = (const float*)d_in[4];
    const float* Wf = (const float*)d_in[5];
    const float* bf = (const float*)d_in[6];
    const int* steps = (const int*)d_in[7];

    float* out = (float*)d_out;
    const int Btot = in_sizes[0] / 64;     // 262144
    const int blocks = Btot / 64;          // 4096

    leapfrog_r11_kernel<<<blocks, THREADS>>>(x, v, f, U, W, Wf, bf, steps, out, Btot);
}

// round 12
// speedup vs baseline: 1.1843x; 1.0781x over previous
#include <cuda_runtime.h>
#include <stdint.h>

constexpr int THREADS = 128;
constexpr float HSTEP  = 0.05f;     // 0.5 * dt_eff
constexpr float DT_EFF = 0.1f;
constexpr float CMU_H  = 0.00125f;  // 0.5 * h * FRICTION_SCALE
constexpr float TWO_PI     = 6.2831853071795864769f;
constexpr float INV_TWO_PI = 0.15915494309189533577f;

// ---------------- helpers ----------------
__device__ __forceinline__ uint32_t bf2(float lo, float hi){
    uint32_t r;
    asm("cvt.rn.bf16x2.f32 %0, %1, %2;" : "=r"(r) : "f"(hi), "f"(lo));
    return r;
}
__device__ __forceinline__ void split2(float x0, float x1, uint32_t& hi, uint32_t& lo){
    hi = bf2(x0, x1);
    float h0 = __uint_as_float(hi << 16);
    float h1 = __uint_as_float(hi & 0xFFFF0000u);
    lo = bf2(x0 - h0, x1 - h1);
}
__device__ __forceinline__ float tanha(float x){
    float y; asm("tanh.approx.f32 %0, %1;" : "=f"(y) : "f"(x)); return y;
}
__device__ __forceinline__ float rdenf(float gate){
    float z = CMU_H * (1.0f + tanha(0.5f * gate));
    return fmaf(z, z, 1.0f) - z;
}
__device__ __forceinline__ void mma(float* c, uint32_t a0, uint32_t a1, uint32_t a2, uint32_t a3,
                                    uint32_t b0, uint32_t b1){
    asm("mma.sync.aligned.m16n8k16.row.col.f32.bf16.bf16.f32 "
        "{%0,%1,%2,%3}, {%4,%5,%6,%7}, {%8,%9}, {%0,%1,%2,%3};"
        : "+f"(c[0]), "+f"(c[1]), "+f"(c[2]), "+f"(c[3])
        : "r"(a0), "r"(a1), "r"(a2), "r"(a3), "r"(b0), "r"(b1));
}
// pair-scoped named barrier: warps {w, w^2} (64 threads) only
__device__ __forceinline__ void pairbar(int q){
    asm volatile("bar.sync %0, %1;" :: "r"(q + 1), "r"(64) : "memory");
}

// =====================================================================
// CTA = 128 thr = 4 warps. q = wid&1 selects a 16-row block, hh = wid>>1
// selects a 32-column half. Thread (g=lane>>2, m=lane&3) owns rows
// {g, g+8} and cols 32*hh + 8t + 2m + e; state idx = rr*8 + 2t + e.
// Warp pair {wid, wid^2} shares a row block; K-split partials reduced
// through padded SMEM with PAIR-scoped named barriers (not CTA-wide).
// g2 fused with the state update using 2-way parallel accumulators.
// =====================================================================
__global__ void __launch_bounds__(THREADS, 3)
leapfrog_r12_kernel(const float* __restrict__ x_in, const float* __restrict__ v_in,
                    const float* __restrict__ f_in, const float* __restrict__ U_in,
                    const float* __restrict__ W_in, const float* __restrict__ Wf_in,
                    const float* __restrict__ bf_in, const int* __restrict__ steps_ptr,
                    float* __restrict__ out, int Btot)
{
    __shared__ uint4 sWf[8 * 32 * 5];   // gate B-frags [ktg][lane][4 uint4 + pad]
    __shared__ uint4 sUl[32 * 5];       // U lo-frags  [lane][ktg 0..3 + pad]
    __shared__ uint4 sWl[32 * 5];       // W lo-frags  [lane][j 0..3 + pad]
    __shared__ float sBias[64];
    __shared__ float sExA[128 * 12];    // a-partial exchange (8 used, stride 12)
    __shared__ float sExB[128 * 28];    // fused exchange (24 used, stride 28)

    const int tid = threadIdx.x, wid = tid >> 5, lane = tid & 31;
    const int g = lane >> 2, m = lane & 3;
    const int q  = wid & 1;        // row-block (also names the pair barrier)
    const int hh = wid >> 1;       // column half
    const int r0 = blockIdx.x * 32 + q * 16 + g;
    const int cbase = 32 * hh + 2 * m;
    const int self    = (wid * 32 + lane);
    const int partner = ((wid ^ 2) * 32 + lane);

    // ---- gate B-frag table: Wf [64][128] -> B[n][k], all 8 k-tiles ----
    #pragma unroll
    for (int t = 0; t < 2; t++) {
        int kt = wid + 4 * t;
        #pragma unroll
        for (int j = 0; j < 4; j++) {
            const float* w0 = Wf_in + (8 * (2 * j)     + g) * 128 + 16 * kt;
            const float* w1 = Wf_in + (8 * (2 * j + 1) + g) * 128 + 16 * kt;
            uint4 qq;
            qq.x = bf2(w0[2 * m],     w0[2 * m + 1]);
            qq.y = bf2(w0[8 + 2 * m], w0[9 + 2 * m]);
            qq.z = bf2(w1[2 * m],     w1[2 * m + 1]);
            qq.w = bf2(w1[8 + 2 * m], w1[9 + 2 * m]);
            sWf[(kt * 32 + lane) * 5 + j] = qq;
        }
    }

    // ---- U frags (this warp's K-half): hi in regs, lo in smem ----
    uint32_t Uh[2][2][2];   // [ktl][nt][pair]
    {
        #pragma unroll
        for (int ktl = 0; ktl < 2; ktl++) {
            int ktg = 2 * hh + ktl;
            uint32_t lo[2][2];
            #pragma unroll
            for (int nt = 0; nt < 2; nt++) {
                const float* up = U_in + (8 * nt + g) * 64 + 16 * ktg;
                split2(up[2 * m],     up[2 * m + 1], Uh[ktl][nt][0], lo[nt][0]);
                split2(up[8 + 2 * m], up[9 + 2 * m], Uh[ktl][nt][1], lo[nt][1]);
            }
            if (q == 0)
                sUl[lane * 5 + ktg] = make_uint4(lo[0][0], lo[0][1], lo[1][0], lo[1][1]);
        }
    }

    // ---- W frags (this warp's N-half): hi in regs, lo in smem ----
    uint32_t Wh[4][2];      // [local n-tile j][pair]
    {
        uint32_t wlo[4][2];
        #pragma unroll
        for (int j = 0; j < 4; j++) {
            int n = 8 * (4 * hh + j) + g;
            split2(W_in[(2 * m) * 64 + n],     W_in[(2 * m + 1) * 64 + n], Wh[j][0], wlo[j][0]);
            split2(W_in[(2 * m + 8) * 64 + n], W_in[(2 * m + 9) * 64 + n], Wh[j][1], wlo[j][1]);
        }
        if (q == 0) {
            #pragma unroll
            for (int jj = 0; jj < 2; jj++)
                sWl[lane * 5 + 2 * hh + jj] =
                    make_uint4(wlo[2 * jj][0], wlo[2 * jj][1], wlo[2 * jj + 1][0], wlo[2 * jj + 1][1]);
        }
    }
    if (tid < 64) sBias[tid] = bf_in[tid];

    // ---- state into registers (16 per array) ----
    float xr[16], vr[16], fr[16], rden[16];
    #pragma unroll
    for (int rr = 0; rr < 2; rr++) {
        const size_t base = (size_t)(r0 + 8 * rr) * 64 + cbase;
        #pragma unroll
        for (int t = 0; t < 4; t++) {
            float2 tt;
            tt = *(const float2*)(x_in + base + 8 * t); xr[rr * 8 + 2 * t] = tt.x; xr[rr * 8 + 2 * t + 1] = tt.y;
            tt = *(const float2*)(v_in + base + 8 * t); vr[rr * 8 + 2 * t] = tt.x; vr[rr * 8 + 2 * t + 1] = tt.y;
            tt = *(const float2*)(f_in + base + 8 * t); fr[rr * 8 + 2 * t] = tt.x; fr[rr * 8 + 2 * t + 1] = tt.y;
        }
    }
    __syncthreads();   // one CTA-wide barrier after weight tables; loop uses pair barriers

    float aC[2][4];     // reduced a (v.U^T), full R=16

    // ---- one g1 k-block (this warp's K-half tile ktl) ----
    auto g1_block = [&](int ktl, float aH[2][4], float aL[2][4]){
        uint32_t ah0, ah1, ah2, ah3, al0, al1, al2, al3;
        split2(vr[4 * ktl],      vr[4 * ktl + 1], ah0, al0);
        split2(vr[8 + 4 * ktl],  vr[9 + 4 * ktl], ah1, al1);
        split2(vr[4 * ktl + 2],  vr[4 * ktl + 3], ah2, al2);
        split2(vr[10 + 4 * ktl], vr[11 + 4 * ktl], ah3, al3);
        uint4 ql = sUl[lane * 5 + 2 * hh + ktl];
        mma(aH[0], ah0, ah1, ah2, ah3, Uh[ktl][0][0], Uh[ktl][0][1]);
        mma(aH[1], ah0, ah1, ah2, ah3, Uh[ktl][1][0], Uh[ktl][1][1]);
        mma(aL[0], ah0, ah1, ah2, ah3, ql.x, ql.y);
        mma(aL[1], ah0, ah1, ah2, ah3, ql.z, ql.w);
        mma(aL[0], al0, al1, al2, al3, Uh[ktl][0][0], Uh[ktl][0][1]);
        mma(aL[1], al0, al1, al2, al3, Uh[ktl][1][0], Uh[ktl][1][1]);
    };

    // ---- standalone g1 partial + pair exchange through sExA ----
    auto g1_reduce = [&](){
        float aH[2][4], aL[2][4];
        #pragma unroll
        for (int nt = 0; nt < 2; nt++)
            #pragma unroll
            for (int k = 0; k < 4; k++) { aH[nt][k] = 0.f; aL[nt][k] = 0.f; }
        g1_block(0, aH, aL);
        g1_block(1, aH, aL);
        #pragma unroll
        for (int nt = 0; nt < 2; nt++) {
            float4 p = make_float4(aH[nt][0] + aL[nt][0], aH[nt][1] + aL[nt][1],
                                   aH[nt][2] + aL[nt][2], aH[nt][3] + aL[nt][3]);
            *(float4*)&sExA[self * 12 + 4 * nt] = p;
            aC[nt][0] = p.x; aC[nt][1] = p.y; aC[nt][2] = p.z; aC[nt][3] = p.w;
        }
        pairbar(q);
        #pragma unroll
        for (int nt = 0; nt < 2; nt++) {
            float4 p = *(const float4*)&sExA[partner * 12 + 4 * nt];
            aC[nt][0] += p.x; aC[nt][1] += p.y; aC[nt][2] += p.z; aC[nt][3] += p.w;
        }
    };

    // ---- fused: gate partial (+ optional g1 partial) + pair exchange via sExB ----
    auto fused_gate = [&](bool with_g1){
        float gc[8][4];
        #pragma unroll
        for (int nt = 0; nt < 8; nt++)
            #pragma unroll
            for (int k = 0; k < 4; k++) gc[nt][k] = 0.0f;
        float aH[2][4], aL[2][4];
        if (with_g1) {
            #pragma unroll
            for (int nt = 0; nt < 2; nt++)
                #pragma unroll
                for (int k = 0; k < 4; k++) { aH[nt][k] = 0.f; aL[nt][k] = 0.f; }
        }
        uint32_t cs[2][4];
        #pragma unroll
        for (int ktl = 0; ktl < 2; ktl++) {
            float s0, c0, s1, c1;
            uint32_t a0, a1, a2, a3;
            __sincosf(xr[4 * ktl],      &s0, &c0);
            __sincosf(xr[4 * ktl + 1],  &s1, &c1);
            a0 = bf2(s0, s1); cs[ktl][0] = bf2(c0, c1);
            __sincosf(xr[8 + 4 * ktl],  &s0, &c0);
            __sincosf(xr[9 + 4 * ktl],  &s1, &c1);
            a1 = bf2(s0, s1); cs[ktl][1] = bf2(c0, c1);
            __sincosf(xr[4 * ktl + 2],  &s0, &c0);
            __sincosf(xr[4 * ktl + 3],  &s1, &c1);
            a2 = bf2(s0, s1); cs[ktl][2] = bf2(c0, c1);
            __sincosf(xr[10 + 4 * ktl], &s0, &c0);
            __sincosf(xr[11 + 4 * ktl], &s1, &c1);
            a3 = bf2(s0, s1); cs[ktl][3] = bf2(c0, c1);
            int ktg = 2 * hh + ktl;   // sin k-tile
            #pragma unroll
            for (int j = 0; j < 4; j++) {
                uint4 qq = sWf[(ktg * 32 + lane) * 5 + j];
                mma(gc[2 * j],     a0, a1, a2, a3, qq.x, qq.y);
                mma(gc[2 * j + 1], a0, a1, a2, a3, qq.z, qq.w);
            }
            if (with_g1) g1_block(ktl, aH, aL);
        }
        #pragma unroll
        for (int ktl = 0; ktl < 2; ktl++) {
            int ktg = 4 + 2 * hh + ktl;   // cos k-tile
            #pragma unroll
            for (int j = 0; j < 4; j++) {
                uint4 qq = sWf[(ktg * 32 + lane) * 5 + j];
                mma(gc[2 * j],     cs[ktl][0], cs[ktl][1], cs[ktl][2], cs[ktl][3], qq.x, qq.y);
                mma(gc[2 * j + 1], cs[ktl][0], cs[ktl][1], cs[ktl][2], cs[ktl][3], qq.z, qq.w);
            }
        }
        // exchange: a-partial [0..7] + other-half gate partial [8..23]
        if (with_g1) {
            #pragma unroll
            for (int nt = 0; nt < 2; nt++) {
                float4 p = make_float4(aH[nt][0] + aL[nt][0], aH[nt][1] + aL[nt][1],
                                       aH[nt][2] + aL[nt][2], aH[nt][3] + aL[nt][3]);
                *(float4*)&sExB[self * 28 + 4 * nt] = p;
                aC[nt][0] = p.x; aC[nt][1] = p.y; aC[nt][2] = p.z; aC[nt][3] = p.w;
            }
        }
        const int oh = 1 - hh;
        #pragma unroll
        for (int j = 0; j < 4; j++)
            *(float4*)&sExB[self * 28 + 8 + 4 * j] = *(const float4*)gc[4 * oh + j];
        pairbar(q);
        if (with_g1) {
            #pragma unroll
            for (int nt = 0; nt < 2; nt++) {
                float4 p = *(const float4*)&sExB[partner * 28 + 4 * nt];
                aC[nt][0] += p.x; aC[nt][1] += p.y; aC[nt][2] += p.z; aC[nt][3] += p.w;
            }
        }
        #pragma unroll
        for (int j = 0; j < 4; j++) {
            float4 p = *(const float4*)&sExB[partner * 28 + 8 + 4 * j];
            float g0 = gc[4 * hh + j][0] + p.x;
            float g1v = gc[4 * hh + j][1] + p.y;
            float g2v = gc[4 * hh + j][2] + p.z;
            float g3 = gc[4 * hh + j][3] + p.w;
            float2 bb = *(const float2*)(sBias + 32 * hh + 8 * j + 2 * m);
            rden[2 * j]     = rdenf(g0 + bb.x);
            rden[2 * j + 1] = rdenf(g1v + bb.y);
            rden[8 + 2 * j] = rdenf(g2v + bb.x);
            rden[9 + 2 * j] = rdenf(g3 + bb.y);
        }
    };

    // ---- g2 fused with state update, 2-way parallel accumulators ----
    auto g2half = [&](bool first){
        uint32_t h0, h1, h2, h3, l0, l1, l2, l3;
        split2(aC[0][0] * aC[0][0], aC[0][1] * aC[0][1], h0, l0);
        split2(aC[0][2] * aC[0][2], aC[0][3] * aC[0][3], h1, l1);
        split2(aC[1][0] * aC[1][0], aC[1][1] * aC[1][1], h2, l2);
        split2(aC[1][2] * aC[1][2], aC[1][3] * aC[1][3], h3, l3);
        #pragma unroll
        for (int jj = 0; jj < 2; jj++) {
            uint4 ql = sWl[lane * 5 + 2 * hh + jj];
            uint32_t Wlf[2][2] = {{ql.x, ql.y}, {ql.z, ql.w}};
            #pragma unroll
            for (int u = 0; u < 2; u++) {
                int j = 2 * jj + u;
                float gA[4] = {0.f, 0.f, 0.f, 0.f};   // hh then lo*hi (depth 2)
                float gB[4] = {0.f, 0.f, 0.f, 0.f};   // hi*lo (depth 1, parallel)
                mma(gA, h0, h1, h2, h3, Wh[j][0], Wh[j][1]);
                mma(gB, h0, h1, h2, h3, Wlf[u][0], Wlf[u][1]);
                mma(gA, l0, l1, l2, l3, Wh[j][0], Wh[j][1]);
                #pragma unroll
                for (int k = 0; k < 4; k++) {
                    int i = (k >> 1) * 8 + 2 * j + (k & 1);
                    float gm = gA[k] + gB[k];
                    float vn = (vr[i] + HSTEP * (fr[i] - gm)) * rden[i];
                    vr[i] = vn;
                    if (first) xr[i] = fmaf(DT_EFF, vn, xr[i]);
                }
            }
        }
    };

    // ---- initial friction at x0 ----
    fused_gate(false);

    // ---- main loop (pair barriers only) ----
    const int steps = steps_ptr[0];
    for (int s = 0; s < steps; s++) {
        g1_reduce();               // a(v), reduced across K-halves
        g2half(true);              // v_half, x update (rden = mu at old x)
        fused_gate(true);          // mu(x_new) + a(v_half), reduced
        g2half(false);             // final v
    }

    // ---- output: wrap x, write x then v ----
    #pragma unroll
    for (int rr = 0; rr < 2; rr++) {
        const size_t base = (size_t)(r0 + 8 * rr) * 64 + cbase;
        #pragma unroll
        for (int t = 0; t < 4; t++) {
            float X0 = xr[rr * 8 + 2 * t], X1 = xr[rr * 8 + 2 * t + 1];
            float2 qx;
            qx.x = fmaf(-TWO_PI, rintf(X0 * INV_TWO_PI), X0);
            qx.y = fmaf(-TWO_PI, rintf(X1 * INV_TWO_PI), X1);
            *(float2*)(out + base + 8 * t) = qx;
            float2 qv = make_float2(vr[rr * 8 + 2 * t], vr[rr * 8 + 2 * t + 1]);
            *(float2*)(out + (size_t)Btot * 64 + base + 8 * t) = qv;
        }
    }
}

extern "C" void kernel_launch(void* const* d_in, const int* in_sizes, int n_in,
                              void* d_out, int out_size)
{
    const float* x  = (const float*)d_in[0];
    const float* v  = (const float*)d_in[1];
    const float* f  = (const float*)d_in[2];
    const float* U  = (const float*)d_in[3];
    const float* W  = (const float*)d_in[4];
    const float* Wf = (const float*)d_in[5];
    const float* bf = (const float*)d_in[6];
    const int* steps = (const int*)d_in[7];

    float* out = (float*)d_out;
    const int Btot = in_sizes[0] / 64;     // 262144
    const int blocks = Btot / 32;          // 8192 (32 rows per CTA, 4 warps)

    leapfrog_r12_kernel<<<blocks, THREADS>>>(x, v, f, U, W, Wf, bf, steps, out, Btot);
}

// round 13
// speedup vs baseline: 1.2139x; 1.0250x over previous
#include <cuda_runtime.h>
#include <stdint.h>

constexpr int THREADS = 128;
constexpr float HSTEP  = 0.05f;     // 0.5 * dt_eff
constexpr float DT_EFF = 0.1f;
constexpr float CMU_H  = 0.00125f;  // 0.5 * h * FRICTION_SCALE
constexpr float TWO_PI     = 6.2831853071795864769f;
constexpr float INV_TWO_PI = 0.15915494309189533577f;

// ---------------- helpers ----------------
__device__ __forceinline__ uint32_t bf2(float lo, float hi){
    uint32_t r;
    asm("cvt.rn.bf16x2.f32 %0, %1, %2;" : "=r"(r) : "f"(hi), "f"(lo));
    return r;
}
__device__ __forceinline__ void split2(float x0, float x1, uint32_t& hi, uint32_t& lo){
    hi = bf2(x0, x1);
    float h0 = __uint_as_float(hi << 16);
    float h1 = __uint_as_float(hi & 0xFFFF0000u);
    lo = bf2(x0 - h0, x1 - h1);
}
__device__ __forceinline__ float tanha(float x){
    float y; asm("tanh.approx.f32 %0, %1;" : "=f"(y) : "f"(x)); return y;
}
__device__ __forceinline__ float rdenf(float gate){
    float z = CMU_H * (1.0f + tanha(0.5f * gate));
    return fmaf(z, z, 1.0f) - z;
}
__device__ __forceinline__ void mma(float* c, uint32_t a0, uint32_t a1, uint32_t a2, uint32_t a3,
                                    uint32_t b0, uint32_t b1){
    asm("mma.sync.aligned.m16n8k16.row.col.f32.bf16.bf16.f32 "
        "{%0,%1,%2,%3}, {%4,%5,%6,%7}, {%8,%9}, {%0,%1,%2,%3};"
        : "+f"(c[0]), "+f"(c[1]), "+f"(c[2]), "+f"(c[3])
        : "r"(a0), "r"(a1), "r"(a2), "r"(a3), "r"(b0), "r"(b1));
}
// pair-scoped named barrier: warps {w, w^2} (64 threads) only
__device__ __forceinline__ void pairbar(int q){
    asm volatile("bar.sync %0, %1;" :: "r"(q + 1), "r"(64) : "memory");
}

// =====================================================================
// CTA = 128 thr = 4 warps. q = wid&1 selects a 16-row block, hh = wid>>1
// selects a 32-column half. Thread (g=lane>>2, m=lane&3) owns rows
// {g, g+8} and cols 32*hh + 8t + 2m + e; state idx = rr*8 + 2t + e.
// Warp pair {wid, wid^2} shares a row block; K-split partials reduced
// through padded SMEM with PAIR-scoped named barriers.
// R13: U/W lo-frags live in REGISTERS (no per-step reload), cos MMAs
// interleaved into the ktl loop (no cos stash).
// =====================================================================
__global__ void __launch_bounds__(THREADS, 3)
leapfrog_r13_kernel(const float* __restrict__ x_in, const float* __restrict__ v_in,
                    const float* __restrict__ f_in, const float* __restrict__ U_in,
                    const float* __restrict__ W_in, const float* __restrict__ Wf_in,
                    const float* __restrict__ bf_in, const int* __restrict__ steps_ptr,
                    float* __restrict__ out, int Btot)
{
    __shared__ uint4 sWf[8 * 32 * 5];   // gate B-frags [ktg][lane][4 uint4 + pad]
    __shared__ float sBias[64];
    __shared__ float sExA[128 * 12];    // a-partial exchange (8 used, stride 12)
    __shared__ float sExB[128 * 28];    // fused exchange (24 used, stride 28)

    const int tid = threadIdx.x, wid = tid >> 5, lane = tid & 31;
    const int g = lane >> 2, m = lane & 3;
    const int q  = wid & 1;        // row-block (names the pair barrier)
    const int hh = wid >> 1;       // column half
    const int r0 = blockIdx.x * 32 + q * 16 + g;
    const int cbase = 32 * hh + 2 * m;
    const int self    = (wid * 32 + lane);
    const int partner = ((wid ^ 2) * 32 + lane);

    // ---- gate B-frag table: Wf [64][128] -> B[n][k], all 8 k-tiles ----
    #pragma unroll
    for (int t = 0; t < 2; t++) {
        int kt = wid + 4 * t;
        #pragma unroll
        for (int j = 0; j < 4; j++) {
            const float* w0 = Wf_in + (8 * (2 * j)     + g) * 128 + 16 * kt;
            const float* w1 = Wf_in + (8 * (2 * j + 1) + g) * 128 + 16 * kt;
            uint4 qq;
            qq.x = bf2(w0[2 * m],     w0[2 * m + 1]);
            qq.y = bf2(w0[8 + 2 * m], w0[9 + 2 * m]);
            qq.z = bf2(w1[2 * m],     w1[2 * m + 1]);
            qq.w = bf2(w1[8 + 2 * m], w1[9 + 2 * m]);
            sWf[(kt * 32 + lane) * 5 + j] = qq;
        }
    }

    // ---- U frags (this warp's K-half): hi AND lo in registers ----
    uint32_t Uh[2][2][2];   // [ktl][nt][pair]
    uint4    Ulr[2];        // lo-frags, per ktl: {nt0 pair0, nt0 pair1, nt1 pair0, nt1 pair1}
    #pragma unroll
    for (int ktl = 0; ktl < 2; ktl++) {
        int ktg = 2 * hh + ktl;
        uint32_t lo[2][2];
        #pragma unroll
        for (int nt = 0; nt < 2; nt++) {
            const float* up = U_in + (8 * nt + g) * 64 + 16 * ktg;
            split2(up[2 * m],     up[2 * m + 1], Uh[ktl][nt][0], lo[nt][0]);
            split2(up[8 + 2 * m], up[9 + 2 * m], Uh[ktl][nt][1], lo[nt][1]);
        }
        Ulr[ktl] = make_uint4(lo[0][0], lo[0][1], lo[1][0], lo[1][1]);
    }

    // ---- W frags (this warp's N-half): hi AND lo in registers ----
    uint32_t Wh[4][2];      // [local n-tile j][pair]
    uint4    Wlr[2];        // lo-frags, per jj: {j=2jj pair0/1, j=2jj+1 pair0/1}
    {
        uint32_t wlo[4][2];
        #pragma unroll
        for (int j = 0; j < 4; j++) {
            int n = 8 * (4 * hh + j) + g;
            split2(W_in[(2 * m) * 64 + n],     W_in[(2 * m + 1) * 64 + n], Wh[j][0], wlo[j][0]);
            split2(W_in[(2 * m + 8) * 64 + n], W_in[(2 * m + 9) * 64 + n], Wh[j][1], wlo[j][1]);
        }
        #pragma unroll
        for (int jj = 0; jj < 2; jj++)
            Wlr[jj] = make_uint4(wlo[2 * jj][0], wlo[2 * jj][1], wlo[2 * jj + 1][0], wlo[2 * jj + 1][1]);
    }
    if (tid < 64) sBias[tid] = bf_in[tid];

    // ---- state into registers (16 per array) ----
    float xr[16], vr[16], fr[16], rden[16];
    #pragma unroll
    for (int rr = 0; rr < 2; rr++) {
        const size_t base = (size_t)(r0 + 8 * rr) * 64 + cbase;
        #pragma unroll
        for (int t = 0; t < 4; t++) {
            float2 tt;
            tt = *(const float2*)(x_in + base + 8 * t); xr[rr * 8 + 2 * t] = tt.x; xr[rr * 8 + 2 * t + 1] = tt.y;
            tt = *(const float2*)(v_in + base + 8 * t); vr[rr * 8 + 2 * t] = tt.x; vr[rr * 8 + 2 * t + 1] = tt.y;
            tt = *(const float2*)(f_in + base + 8 * t); fr[rr * 8 + 2 * t] = tt.x; fr[rr * 8 + 2 * t + 1] = tt.y;
        }
    }
    __syncthreads();   // one CTA-wide barrier after the sWf table; loop uses pair barriers

    float aC[2][4];     // reduced a (v.U^T), full R=16

    // ---- one g1 k-block (this warp's K-half tile ktl) ----
    auto g1_block = [&](int ktl, float aH[2][4], float aL[2][4]){
        uint32_t ah0, ah1, ah2, ah3, al0, al1, al2, al3;
        split2(vr[4 * ktl],      vr[4 * ktl + 1], ah0, al0);
        split2(vr[8 + 4 * ktl],  vr[9 + 4 * ktl], ah1, al1);
        split2(vr[4 * ktl + 2],  vr[4 * ktl + 3], ah2, al2);
        split2(vr[10 + 4 * ktl], vr[11 + 4 * ktl], ah3, al3);
        uint4 ql = Ulr[ktl];
        mma(aH[0], ah0, ah1, ah2, ah3, Uh[ktl][0][0], Uh[ktl][0][1]);
        mma(aH[1], ah0, ah1, ah2, ah3, Uh[ktl][1][0], Uh[ktl][1][1]);
        mma(aL[0], ah0, ah1, ah2, ah3, ql.x, ql.y);
        mma(aL[1], ah0, ah1, ah2, ah3, ql.z, ql.w);
        mma(aL[0], al0, al1, al2, al3, Uh[ktl][0][0], Uh[ktl][0][1]);
        mma(aL[1], al0, al1, al2, al3, Uh[ktl][1][0], Uh[ktl][1][1]);
    };

    // ---- standalone g1 partial + pair exchange through sExA ----
    auto g1_reduce = [&](){
        float aH[2][4], aL[2][4];
        #pragma unroll
        for (int nt = 0; nt < 2; nt++)
            #pragma unroll
            for (int k = 0; k < 4; k++) { aH[nt][k] = 0.f; aL[nt][k] = 0.f; }
        g1_block(0, aH, aL);
        g1_block(1, aH, aL);
        #pragma unroll
        for (int nt = 0; nt < 2; nt++) {
            float4 p = make_float4(aH[nt][0] + aL[nt][0], aH[nt][1] + aL[nt][1],
                                   aH[nt][2] + aL[nt][2], aH[nt][3] + aL[nt][3]);
            *(float4*)&sExA[self * 12 + 4 * nt] = p;
            aC[nt][0] = p.x; aC[nt][1] = p.y; aC[nt][2] = p.z; aC[nt][3] = p.w;
        }
        pairbar(q);
        #pragma unroll
        for (int nt = 0; nt < 2; nt++) {
            float4 p = *(const float4*)&sExA[partner * 12 + 4 * nt];
            aC[nt][0] += p.x; aC[nt][1] += p.y; aC[nt][2] += p.z; aC[nt][3] += p.w;
        }
    };

    // ---- fused: gate partial (+ optional g1), sin/cos interleaved per ktl ----
    auto fused_gate = [&](bool with_g1){
        float gc[8][4];
        #pragma unroll
        for (int nt = 0; nt < 8; nt++)
            #pragma unroll
            for (int k = 0; k < 4; k++) gc[nt][k] = 0.0f;
        float aH[2][4], aL[2][4];
        if (with_g1) {
            #pragma unroll
            for (int nt = 0; nt < 2; nt++)
                #pragma unroll
                for (int k = 0; k < 4; k++) { aH[nt][k] = 0.f; aL[nt][k] = 0.f; }
        }
        #pragma unroll
        for (int ktl = 0; ktl < 2; ktl++) {
            float s0, c0, s1, c1;
            uint32_t a0, a1, a2, a3, c0p, c1p, c2p, c3p;
            __sincosf(xr[4 * ktl],      &s0, &c0);
            __sincosf(xr[4 * ktl + 1],  &s1, &c1);
            a0 = bf2(s0, s1); c0p = bf2(c0, c1);
            __sincosf(xr[8 + 4 * ktl],  &s0, &c0);
            __sincosf(xr[9 + 4 * ktl],  &s1, &c1);
            a1 = bf2(s0, s1); c1p = bf2(c0, c1);
            __sincosf(xr[4 * ktl + 2],  &s0, &c0);
            __sincosf(xr[4 * ktl + 3],  &s1, &c1);
            a2 = bf2(s0, s1); c2p = bf2(c0, c1);
            __sincosf(xr[10 + 4 * ktl], &s0, &c0);
            __sincosf(xr[11 + 4 * ktl], &s1, &c1);
            a3 = bf2(s0, s1); c3p = bf2(c0, c1);
            int ktgS = 2 * hh + ktl;       // sin k-tile
            int ktgC = 4 + 2 * hh + ktl;   // cos k-tile
            #pragma unroll
            for (int j = 0; j < 4; j++) {
                uint4 qs = sWf[(ktgS * 32 + lane) * 5 + j];
                mma(gc[2 * j],     a0, a1, a2, a3, qs.x, qs.y);
                mma(gc[2 * j + 1], a0, a1, a2, a3, qs.z, qs.w);
                uint4 qc = sWf[(ktgC * 32 + lane) * 5 + j];
                mma(gc[2 * j],     c0p, c1p, c2p, c3p, qc.x, qc.y);
                mma(gc[2 * j + 1], c0p, c1p, c2p, c3p, qc.z, qc.w);
            }
            if (with_g1) g1_block(ktl, aH, aL);
        }
        // exchange: a-partial [0..7] + other-half gate partial [8..23]
        if (with_g1) {
            #pragma unroll
            for (int nt = 0; nt < 2; nt++) {
                float4 p = make_float4(aH[nt][0] + aL[nt][0], aH[nt][1] + aL[nt][1],
                                       aH[nt][2] + aL[nt][2], aH[nt][3] + aL[nt][3]);
                *(float4*)&sExB[self * 28 + 4 * nt] = p;
                aC[nt][0] = p.x; aC[nt][1] = p.y; aC[nt][2] = p.z; aC[nt][3] = p.w;
            }
        }
        const int oh = 1 - hh;
        #pragma unroll
        for (int j = 0; j < 4; j++)
            *(float4*)&sExB[self * 28 + 8 + 4 * j] = *(const float4*)gc[4 * oh + j];
        pairbar(q);
        if (with_g1) {
            #pragma unroll
            for (int nt = 0; nt < 2; nt++) {
                float4 p = *(const float4*)&sExB[partner * 28 + 4 * nt];
                aC[nt][0] += p.x; aC[nt][1] += p.y; aC[nt][2] += p.z; aC[nt][3] += p.w;
            }
        }
        #pragma unroll
        for (int j = 0; j < 4; j++) {
            float4 p = *(const float4*)&sExB[partner * 28 + 8 + 4 * j];
            float g0 = gc[4 * hh + j][0] + p.x;
            float g1v = gc[4 * hh + j][1] + p.y;
            float g2v = gc[4 * hh + j][2] + p.z;
            float g3 = gc[4 * hh + j][3] + p.w;
            float2 bb = *(const float2*)(sBias + 32 * hh + 8 * j + 2 * m);
            rden[2 * j]     = rdenf(g0 + bb.x);
            rden[2 * j + 1] = rdenf(g1v + bb.y);
            rden[8 + 2 * j] = rdenf(g2v + bb.x);
            rden[9 + 2 * j] = rdenf(g3 + bb.y);
        }
    };

    // ---- g2 fused with state update, 2-way parallel accumulators ----
    auto g2half = [&](bool first){
        uint32_t h0, h1, h2, h3, l0, l1, l2, l3;
        split2(aC[0][0] * aC[0][0], aC[0][1] * aC[0][1], h0, l0);
        split2(aC[0][2] * aC[0][2], aC[0][3] * aC[0][3], h1, l1);
        split2(aC[1][0] * aC[1][0], aC[1][1] * aC[1][1], h2, l2);
        split2(aC[1][2] * aC[1][2], aC[1][3] * aC[1][3], h3, l3);
        #pragma unroll
        for (int jj = 0; jj < 2; jj++) {
            uint4 ql = Wlr[jj];
            uint32_t Wlf[2][2] = {{ql.x, ql.y}, {ql.z, ql.w}};
            #pragma unroll
            for (int u = 0; u < 2; u++) {
                int j = 2 * jj + u;
                float gA[4] = {0.f, 0.f, 0.f, 0.f};   // hh then lo*hi (depth 2)
                float gB[4] = {0.f, 0.f, 0.f, 0.f};   // hi*lo (depth 1, parallel)
                mma(gA, h0, h1, h2, h3, Wh[j][0], Wh[j][1]);
                mma(gB, h0, h1, h2, h3, Wlf[u][0], Wlf[u][1]);
                mma(gA, l0, l1, l2, l3, Wh[j][0], Wh[j][1]);
                #pragma unroll
                for (int k = 0; k < 4; k++) {
                    int i = (k >> 1) * 8 + 2 * j + (k & 1);
                    float gm = gA[k] + gB[k];
                    float vn = (vr[i] + HSTEP * (fr[i] - gm)) * rden[i];
                    vr[i] = vn;
                    if (first) xr[i] = fmaf(DT_EFF, vn, xr[i]);
                }
            }
        }
    };

    // ---- initial friction at x0 ----
    fused_gate(false);

    // ---- main loop (pair barriers only) ----
    const int steps = steps_ptr[0];
    for (int s = 0; s < steps; s++) {
        g1_reduce();               // a(v), reduced across K-halves
        g2half(true);              // v_half, x update (rden = mu at old x)
        fused_gate(true);          // mu(x_new) + a(v_half), reduced
        g2half(false);             // final v
    }

    // ---- output: wrap x, write x then v ----
    #pragma unroll
    for (int rr = 0; rr < 2; rr++) {
        const size_t base = (size_t)(r0 + 8 * rr) * 64 + cbase;
        #pragma unroll
        for (int t = 0; t < 4; t++) {
            float X0 = xr[rr * 8 + 2 * t], X1 = xr[rr * 8 + 2 * t + 1];
            float2 qx;
            qx.x = fmaf(-TWO_PI, rintf(X0 * INV_TWO_PI), X0);
            qx.y = fmaf(-TWO_PI, rintf(X1 * INV_TWO_PI), X1);
            *(float2*)(out + base + 8 * t) = qx;
            float2 qv = make_float2(vr[rr * 8 + 2 * t], vr[rr * 8 + 2 * t + 1]);
            *(float2*)(out + (size_t)Btot * 64 + base + 8 * t) = qv;
        }
    }
}

extern "C" void kernel_launch(void* const* d_in, const int* in_sizes, int n_in,
                              void* d_out, int out_size)
{
    const float* x  = (const float*)d_in[0];
    const float* v  = (const float*)d_in[1];
    const float* f  = (const float*)d_in[2];
    const float* U  = (const float*)d_in[3];
    const float* W  = (const float*)d_in[4];
    const float* Wf = (const float*)d_in[5];
    const float* bf = (const float*)d_in[6];
    const int* steps = (const int*)d_in[7];

    float* out = (float*)d_out;
    const int Btot = in_sizes[0] / 64;     // 262144
    const int blocks = Btot / 32;          // 8192 (32 rows per CTA, 4 warps)

    leapfrog_r13_kernel<<<blocks, THREADS>>>(x, v, f, U, W, Wf, bf, steps, out, Btot);
}

// round 14
// speedup vs baseline: 1.2433x; 1.0242x over previous
#include <cuda_runtime.h>
#include <stdint.h>

constexpr int THREADS = 128;
constexpr float HSTEP  = 0.05f;     // 0.5 * dt_eff
constexpr float DT_EFF = 0.1f;
constexpr float CMU_H  = 0.00125f;  // 0.5 * h * FRICTION_SCALE
constexpr float TWO_PI     = 6.2831853071795864769f;
constexpr float INV_TWO_PI = 0.15915494309189533577f;

// ---------------- helpers ----------------
__device__ __forceinline__ uint32_t bf2(float lo, float hi){
    uint32_t r;
    asm("cvt.rn.bf16x2.f32 %0, %1, %2;" : "=r"(r) : "f"(hi), "f"(lo));
    return r;
}
__device__ __forceinline__ void split2(float x0, float x1, uint32_t& hi, uint32_t& lo){
    hi = bf2(x0, x1);
    float h0 = __uint_as_float(hi << 16);
    float h1 = __uint_as_float(hi & 0xFFFF0000u);
    lo = bf2(x0 - h0, x1 - h1);
}
__device__ __forceinline__ uint32_t pkh(float lo, float hi){
    uint32_t r; asm("cvt.rn.f16x2.f32 %0, %1, %2;" : "=r"(r) : "f"(hi), "f"(lo)); return r;
}
__device__ __forceinline__ float2 h2f2(uint32_t h){
    float2 r;
    asm("{ .reg .f16 lo, hi; mov.b32 {lo, hi}, %2; cvt.f32.f16 %0, lo; cvt.f32.f16 %1, hi; }"
        : "=f"(r.x), "=f"(r.y) : "r"(h));
    return r;
}
__device__ __forceinline__ float tanha(float x){
    float y; asm("tanh.approx.f32 %0, %1;" : "=f"(y) : "f"(x)); return y;
}
__device__ __forceinline__ float rdenf(float gate){
    float z = CMU_H * (1.0f + tanha(0.5f * gate));
    return fmaf(z, z, 1.0f) - z;
}
__device__ __forceinline__ void mma(float* c, uint32_t a0, uint32_t a1, uint32_t a2, uint32_t a3,
                                    uint32_t b0, uint32_t b1){
    asm("mma.sync.aligned.m16n8k16.row.col.f32.bf16.bf16.f32 "
        "{%0,%1,%2,%3}, {%4,%5,%6,%7}, {%8,%9}, {%0,%1,%2,%3};"
        : "+f"(c[0]), "+f"(c[1]), "+f"(c[2]), "+f"(c[3])
        : "r"(a0), "r"(a1), "r"(a2), "r"(a3), "r"(b0), "r"(b1));
}
// pair-scoped named barrier: warps {w, w^2} (64 threads) only
__device__ __forceinline__ void pairbar(int q){
    asm volatile("bar.sync %0, %1;" :: "r"(q + 1), "r"(64) : "memory");
}

// =====================================================================
// CTA = 128 thr = 4 warps. q = wid&1 selects a 16-row block, hh = wid>>1
// selects a 32-column half. Thread (g=lane>>2, m=lane&3) owns rows
// {g, g+8} and cols 32*hh + 8t + 2m + e; state idx = rr*8 + 2t + e.
// Warp pair {wid, wid^2} shares a row block; K-split partials reduced
// through padded SMEM with PAIR-scoped named barriers.
// R13: U/W lo-frags in registers; R14: gate-partial exchange packed f16x2
// (a-partials stay fp32) -> ~18% less LSU volume.
// =====================================================================
__global__ void __launch_bounds__(THREADS, 3)
leapfrog_r14_kernel(const float* __restrict__ x_in, const float* __restrict__ v_in,
                    const float* __restrict__ f_in, const float* __restrict__ U_in,
                    const float* __restrict__ W_in, const float* __restrict__ Wf_in,
                    const float* __restrict__ bf_in, const int* __restrict__ steps_ptr,
                    float* __restrict__ out, int Btot)
{
    __shared__ uint4 sWf[8 * 32 * 5];   // gate B-frags [ktg][lane][4 uint4 + pad]
    __shared__ float sBias[64];
    __shared__ float sExA[128 * 12];    // a-partial exchange fp32 (8 used, stride 12)
    __shared__ float sExB[128 * 20];    // fused exchange: a fp32 [0..7] + gate f16x2 [8..15]

    const int tid = threadIdx.x, wid = tid >> 5, lane = tid & 31;
    const int g = lane >> 2, m = lane & 3;
    const int q  = wid & 1;        // row-block (names the pair barrier)
    const int hh = wid >> 1;       // column half
    const int r0 = blockIdx.x * 32 + q * 16 + g;
    const int cbase = 32 * hh + 2 * m;
    const int self    = (wid * 32 + lane);
    const int partner = ((wid ^ 2) * 32 + lane);

    // ---- gate B-frag table: Wf [64][128] -> B[n][k], all 8 k-tiles ----
    #pragma unroll
    for (int t = 0; t < 2; t++) {
        int kt = wid + 4 * t;
        #pragma unroll
        for (int j = 0; j < 4; j++) {
            const float* w0 = Wf_in + (8 * (2 * j)     + g) * 128 + 16 * kt;
            const float* w1 = Wf_in + (8 * (2 * j + 1) + g) * 128 + 16 * kt;
            uint4 qq;
            qq.x = bf2(w0[2 * m],     w0[2 * m + 1]);
            qq.y = bf2(w0[8 + 2 * m], w0[9 + 2 * m]);
            qq.z = bf2(w1[2 * m],     w1[2 * m + 1]);
            qq.w = bf2(w1[8 + 2 * m], w1[9 + 2 * m]);
            sWf[(kt * 32 + lane) * 5 + j] = qq;
        }
    }

    // ---- U frags (this warp's K-half): hi AND lo in registers ----
    uint32_t Uh[2][2][2];   // [ktl][nt][pair]
    uint4    Ulr[2];
    #pragma unroll
    for (int ktl = 0; ktl < 2; ktl++) {
        int ktg = 2 * hh + ktl;
        uint32_t lo[2][2];
        #pragma unroll
        for (int nt = 0; nt < 2; nt++) {
            const float* up = U_in + (8 * nt + g) * 64 + 16 * ktg;
            split2(up[2 * m],     up[2 * m + 1], Uh[ktl][nt][0], lo[nt][0]);
            split2(up[8 + 2 * m], up[9 + 2 * m], Uh[ktl][nt][1], lo[nt][1]);
        }
        Ulr[ktl] = make_uint4(lo[0][0], lo[0][1], lo[1][0], lo[1][1]);
    }

    // ---- W frags (this warp's N-half): hi AND lo in registers ----
    uint32_t Wh[4][2];
    uint4    Wlr[2];
    {
        uint32_t wlo[4][2];
        #pragma unroll
        for (int j = 0; j < 4; j++) {
            int n = 8 * (4 * hh + j) + g;
            split2(W_in[(2 * m) * 64 + n],     W_in[(2 * m + 1) * 64 + n], Wh[j][0], wlo[j][0]);
            split2(W_in[(2 * m + 8) * 64 + n], W_in[(2 * m + 9) * 64 + n], Wh[j][1], wlo[j][1]);
        }
        #pragma unroll
        for (int jj = 0; jj < 2; jj++)
            Wlr[jj] = make_uint4(wlo[2 * jj][0], wlo[2 * jj][1], wlo[2 * jj + 1][0], wlo[2 * jj + 1][1]);
    }
    if (tid < 64) sBias[tid] = bf_in[tid];

    // ---- state into registers (16 per array) ----
    float xr[16], vr[16], fr[16], rden[16];
    #pragma unroll
    for (int rr = 0; rr < 2; rr++) {
        const size_t base = (size_t)(r0 + 8 * rr) * 64 + cbase;
        #pragma unroll
        for (int t = 0; t < 4; t++) {
            float2 tt;
            tt = *(const float2*)(x_in + base + 8 * t); xr[rr * 8 + 2 * t] = tt.x; xr[rr * 8 + 2 * t + 1] = tt.y;
            tt = *(const float2*)(v_in + base + 8 * t); vr[rr * 8 + 2 * t] = tt.x; vr[rr * 8 + 2 * t + 1] = tt.y;
            tt = *(const float2*)(f_in + base + 8 * t); fr[rr * 8 + 2 * t] = tt.x; fr[rr * 8 + 2 * t + 1] = tt.y;
        }
    }
    __syncthreads();   // one CTA-wide barrier after the sWf table; loop uses pair barriers

    float aC[2][4];     // reduced a (v.U^T), full R=16

    // ---- one g1 k-block (this warp's K-half tile ktl) ----
    auto g1_block = [&](int ktl, float aH[2][4], float aL[2][4]){
        uint32_t ah0, ah1, ah2, ah3, al0, al1, al2, al3;
        split2(vr[4 * ktl],      vr[4 * ktl + 1], ah0, al0);
        split2(vr[8 + 4 * ktl],  vr[9 + 4 * ktl], ah1, al1);
        split2(vr[4 * ktl + 2],  vr[4 * ktl + 3], ah2, al2);
        split2(vr[10 + 4 * ktl], vr[11 + 4 * ktl], ah3, al3);
        uint4 ql = Ulr[ktl];
        mma(aH[0], ah0, ah1, ah2, ah3, Uh[ktl][0][0], Uh[ktl][0][1]);
        mma(aH[1], ah0, ah1, ah2, ah3, Uh[ktl][1][0], Uh[ktl][1][1]);
        mma(aL[0], ah0, ah1, ah2, ah3, ql.x, ql.y);
        mma(aL[1], ah0, ah1, ah2, ah3, ql.z, ql.w);
        mma(aL[0], al0, al1, al2, al3, Uh[ktl][0][0], Uh[ktl][0][1]);
        mma(aL[1], al0, al1, al2, al3, Uh[ktl][1][0], Uh[ktl][1][1]);
    };

    // ---- standalone g1 partial + pair exchange through sExA ----
    auto g1_reduce = [&](){
        float aH[2][4], aL[2][4];
        #pragma unroll
        for (int nt = 0; nt < 2; nt++)
            #pragma unroll
            for (int k = 0; k < 4; k++) { aH[nt][k] = 0.f; aL[nt][k] = 0.f; }
        g1_block(0, aH, aL);
        g1_block(1, aH, aL);
        #pragma unroll
        for (int nt = 0; nt < 2; nt++) {
            float4 p = make_float4(aH[nt][0] + aL[nt][0], aH[nt][1] + aL[nt][1],
                                   aH[nt][2] + aL[nt][2], aH[nt][3] + aL[nt][3]);
            *(float4*)&sExA[self * 12 + 4 * nt] = p;
            aC[nt][0] = p.x; aC[nt][1] = p.y; aC[nt][2] = p.z; aC[nt][3] = p.w;
        }
        pairbar(q);
        #pragma unroll
        for (int nt = 0; nt < 2; nt++) {
            float4 p = *(const float4*)&sExA[partner * 12 + 4 * nt];
            aC[nt][0] += p.x; aC[nt][1] += p.y; aC[nt][2] += p.z; aC[nt][3] += p.w;
        }
    };

    // ---- fused: gate partial (+ optional g1), f16x2-packed gate exchange ----
    auto fused_gate = [&](bool with_g1){
        float gc[8][4];
        #pragma unroll
        for (int nt = 0; nt < 8; nt++)
            #pragma unroll
            for (int k = 0; k < 4; k++) gc[nt][k] = 0.0f;
        float aH[2][4], aL[2][4];
        if (with_g1) {
            #pragma unroll
            for (int nt = 0; nt < 2; nt++)
                #pragma unroll
                for (int k = 0; k < 4; k++) { aH[nt][k] = 0.f; aL[nt][k] = 0.f; }
        }
        #pragma unroll
        for (int ktl = 0; ktl < 2; ktl++) {
            float s0, c0, s1, c1;
            uint32_t a0, a1, a2, a3, c0p, c1p, c2p, c3p;
            __sincosf(xr[4 * ktl],      &s0, &c0);
            __sincosf(xr[4 * ktl + 1],  &s1, &c1);
            a0 = bf2(s0, s1); c0p = bf2(c0, c1);
            __sincosf(xr[8 + 4 * ktl],  &s0, &c0);
            __sincosf(xr[9 + 4 * ktl],  &s1, &c1);
            a1 = bf2(s0, s1); c1p = bf2(c0, c1);
            __sincosf(xr[4 * ktl + 2],  &s0, &c0);
            __sincosf(xr[4 * ktl + 3],  &s1, &c1);
            a2 = bf2(s0, s1); c2p = bf2(c0, c1);
            __sincosf(xr[10 + 4 * ktl], &s0, &c0);
            __sincosf(xr[11 + 4 * ktl], &s1, &c1);
            a3 = bf2(s0, s1); c3p = bf2(c0, c1);
            int ktgS = 2 * hh + ktl;       // sin k-tile
            int ktgC = 4 + 2 * hh + ktl;   // cos k-tile
            #pragma unroll
            for (int j = 0; j < 4; j++) {
                uint4 qs = sWf[(ktgS * 32 + lane) * 5 + j];
                mma(gc[2 * j],     a0, a1, a2, a3, qs.x, qs.y);
                mma(gc[2 * j + 1], a0, a1, a2, a3, qs.z, qs.w);
                uint4 qc = sWf[(ktgC * 32 + lane) * 5 + j];
                mma(gc[2 * j],     c0p, c1p, c2p, c3p, qc.x, qc.y);
                mma(gc[2 * j + 1], c0p, c1p, c2p, c3p, qc.z, qc.w);
            }
            if (with_g1) g1_block(ktl, aH, aL);
        }
        // exchange: a-partial fp32 [0..7] + other-half gate partial f16x2 [8..15]
        if (with_g1) {
            #pragma unroll
            for (int nt = 0; nt < 2; nt++) {
                float4 p = make_float4(aH[nt][0] + aL[nt][0], aH[nt][1] + aL[nt][1],
                                       aH[nt][2] + aL[nt][2], aH[nt][3] + aL[nt][3]);
                *(float4*)&sExB[self * 20 + 4 * nt] = p;
                aC[nt][0] = p.x; aC[nt][1] = p.y; aC[nt][2] = p.z; aC[nt][3] = p.w;
            }
        }
        const int oh = 1 - hh;
        {
            uint4 q0, q1;
            q0.x = pkh(gc[4 * oh + 0][0], gc[4 * oh + 0][1]);
            q0.y = pkh(gc[4 * oh + 0][2], gc[4 * oh + 0][3]);
            q0.z = pkh(gc[4 * oh + 1][0], gc[4 * oh + 1][1]);
            q0.w = pkh(gc[4 * oh + 1][2], gc[4 * oh + 1][3]);
            q1.x = pkh(gc[4 * oh + 2][0], gc[4 * oh + 2][1]);
            q1.y = pkh(gc[4 * oh + 2][2], gc[4 * oh + 2][3]);
            q1.z = pkh(gc[4 * oh + 3][0], gc[4 * oh + 3][1]);
            q1.w = pkh(gc[4 * oh + 3][2], gc[4 * oh + 3][3]);
            *(uint4*)&sExB[self * 20 + 8]  = q0;
            *(uint4*)&sExB[self * 20 + 12] = q1;
        }
        pairbar(q);
        if (with_g1) {
            #pragma unroll
            for (int nt = 0; nt < 2; nt++) {
                float4 p = *(const float4*)&sExB[partner * 20 + 4 * nt];
                aC[nt][0] += p.x; aC[nt][1] += p.y; aC[nt][2] += p.z; aC[nt][3] += p.w;
            }
        }
        {
            uint4 q0 = *(const uint4*)&sExB[partner * 20 + 8];
            uint4 q1 = *(const uint4*)&sExB[partner * 20 + 12];
            uint32_t pk[8] = {q0.x, q0.y, q0.z, q0.w, q1.x, q1.y, q1.z, q1.w};
            #pragma unroll
            for (int j = 0; j < 4; j++) {
                float2 pA = h2f2(pk[2 * j]);       // partner gc[4hh+j][0], [1]
                float2 pB = h2f2(pk[2 * j + 1]);   // partner gc[4hh+j][2], [3]
                float g0  = gc[4 * hh + j][0] + pA.x;
                float g1v = gc[4 * hh + j][1] + pA.y;
                float g2v = gc[4 * hh + j][2] + pB.x;
                float g3  = gc[4 * hh + j][3] + pB.y;
                float2 bb = *(const float2*)(sBias + 32 * hh + 8 * j + 2 * m);
                rden[2 * j]     = rdenf(g0 + bb.x);
                rden[2 * j + 1] = rdenf(g1v + bb.y);
                rden[8 + 2 * j] = rdenf(g2v + bb.x);
                rden[9 + 2 * j] = rdenf(g3 + bb.y);
            }
        }
    };

    // ---- g2 fused with state update, 2-way parallel accumulators ----
    auto g2half = [&](bool first){
        uint32_t h0, h1, h2, h3, l0, l1, l2, l3;
        split2(aC[0][0] * aC[0][0], aC[0][1] * aC[0][1], h0, l0);
        split2(aC[0][2] * aC[0][2], aC[0][3] * aC[0][3], h1, l1);
        split2(aC[1][0] * aC[1][0], aC[1][1] * aC[1][1], h2, l2);
        split2(aC[1][2] * aC[1][2], aC[1][3] * aC[1][3], h3, l3);
        #pragma unroll
        for (int jj = 0; jj < 2; jj++) {
            uint4 ql = Wlr[jj];
            uint32_t Wlf[2][2] = {{ql.x, ql.y}, {ql.z, ql.w}};
            #pragma unroll
            for (int u = 0; u < 2; u++) {
                int j = 2 * jj + u;
                float gA[4] = {0.f, 0.f, 0.f, 0.f};
                float gB[4] = {0.f, 0.f, 0.f, 0.f};
                mma(gA, h0, h1, h2, h3, Wh[j][0], Wh[j][1]);
                mma(gB, h0, h1, h2, h3, Wlf[u][0], Wlf[u][1]);
                mma(gA, l0, l1, l2, l3, Wh[j][0], Wh[j][1]);
                #pragma unroll
                for (int k = 0; k < 4; k++) {
                    int i = (k >> 1) * 8 + 2 * j + (k & 1);
                    float gm = gA[k] + gB[k];
                    float vn = (vr[i] + HSTEP * (fr[i] - gm)) * rden[i];
                    vr[i] = vn;
                    if (first) xr[i] = fmaf(DT_EFF, vn, xr[i]);
                }
            }
        }
    };

    // ---- initial friction at x0 ----
    fused_gate(false);

    // ---- main loop (pair barriers only) ----
    const int steps = steps_ptr[0];
    for (int s = 0; s < steps; s++) {
        g1_reduce();               // a(v), reduced across K-halves
        g2half(true);              // v_half, x update (rden = mu at old x)
        fused_gate(true);          // mu(x_new) + a(v_half), reduced
        g2half(false);             // final v
    }

    // ---- output: wrap x, write x then v ----
    #pragma unroll
    for (int rr = 0; rr < 2; rr++) {
        const size_t base = (size_t)(r0 + 8 * rr) * 64 + cbase;
        #pragma unroll
        for (int t = 0; t < 4; t++) {
            float X0 = xr[rr * 8 + 2 * t], X1 = xr[rr * 8 + 2 * t + 1];
            float2 qx;
            qx.x = fmaf(-TWO_PI, rintf(X0 * INV_TWO_PI), X0);
            qx.y = fmaf(-TWO_PI, rintf(X1 * INV_TWO_PI), X1);
            *(float2*)(out + base + 8 * t) = qx;
            float2 qv = make_float2(vr[rr * 8 + 2 * t], vr[rr * 8 + 2 * t + 1]);
            *(float2*)(out + (size_t)Btot * 64 + base + 8 * t) = qv;
        }
    }
}

extern "C" void kernel_launch(void* const* d_in, const int* in_sizes, int n_in,
                              void* d_out, int out_size)
{
    const float* x  = (const float*)d_in[0];
    const float* v  = (const float*)d_in[1];
    const float* f  = (const float*)d_in[2];
    const float* U  = (const float*)d_in[3];
    const float* W  = (const float*)d_in[4];
    const float* Wf = (const float*)d_in[5];
    const float* bf = (const float*)d_in[6];
    const int* steps = (const int*)d_in[7];

    float* out = (float*)d_out;
    const int Btot = in_sizes[0] / 64;     // 262144
    const int blocks = Btot / 32;          // 8192 (32 rows per CTA, 4 warps)

    leapfrog_r14_kernel<<<blocks, THREADS>>>(x, v, f, U, W, Wf, bf, steps, out, Btot);
}

// round 15
// speedup vs baseline: 1.6055x; 1.2913x over previous
#include <cuda_runtime.h>
#include <stdint.h>

constexpr int THREADS = 128;
constexpr int NBLK    = 444;        // 148 SMs x 3 resident CTAs: one persistent wave
constexpr float HSTEP  = 0.05f;     // 0.5 * dt_eff
constexpr float DT_EFF = 0.1f;
constexpr float CMU_H  = 0.00125f;  // 0.5 * h * FRICTION_SCALE
constexpr float TWO_PI     = 6.2831853071795864769f;
constexpr float INV_TWO_PI = 0.15915494309189533577f;

// ---------------- helpers ----------------
__device__ __forceinline__ uint32_t bf2(float lo, float hi){
    uint32_t r;
    asm("cvt.rn.bf16x2.f32 %0, %1, %2;" : "=r"(r) : "f"(hi), "f"(lo));
    return r;
}
__device__ __forceinline__ void split2(float x0, float x1, uint32_t& hi, uint32_t& lo){
    hi = bf2(x0, x1);
    float h0 = __uint_as_float(hi << 16);
    float h1 = __uint_as_float(hi & 0xFFFF0000u);
    lo = bf2(x0 - h0, x1 - h1);
}
__device__ __forceinline__ uint32_t pkh(float lo, float hi){
    uint32_t r; asm("cvt.rn.f16x2.f32 %0, %1, %2;" : "=r"(r) : "f"(hi), "f"(lo)); return r;
}
__device__ __forceinline__ float2 h2f2(uint32_t h){
    float2 r;
    asm("{ .reg .f16 lo, hi; mov.b32 {lo, hi}, %2; cvt.f32.f16 %0, lo; cvt.f32.f16 %1, hi; }"
        : "=f"(r.x), "=f"(r.y) : "r"(h));
    return r;
}
__device__ __forceinline__ float tanha(float x){
    float y; asm("tanh.approx.f32 %0, %1;" : "=f"(y) : "f"(x)); return y;
}
__device__ __forceinline__ float rdenf(float gate){
    float z = CMU_H * (1.0f + tanha(0.5f * gate));
    return fmaf(z, z, 1.0f) - z;
}
__device__ __forceinline__ void mma(float* c, uint32_t a0, uint32_t a1, uint32_t a2, uint32_t a3,
                                    uint32_t b0, uint32_t b1){
    asm("mma.sync.aligned.m16n8k16.row.col.f32.bf16.bf16.f32 "
        "{%0,%1,%2,%3}, {%4,%5,%6,%7}, {%8,%9}, {%0,%1,%2,%3};"
        : "+f"(c[0]), "+f"(c[1]), "+f"(c[2]), "+f"(c[3])
        : "r"(a0), "r"(a1), "r"(a2), "r"(a3), "r"(b0), "r"(b1));
}
// pair-scoped named barrier: warps {w, w^2} (64 threads) only
__device__ __forceinline__ void pairbar(int q){
    asm volatile("bar.sync %0, %1;" :: "r"(q + 1), "r"(64) : "memory");
}

// =====================================================================
// Persistent kernel: 444 CTAs build the weight-fragment tables ONCE and
// loop over tiles (32 rows each) with stride 444. Per-tile body identical
// to R14: pair-split K, pair-scoped barriers, f16-packed gate exchange,
// U/W frags in registers.
// =====================================================================
__global__ void __launch_bounds__(THREADS, 3)
leapfrog_r15_kernel(const float* __restrict__ x_in, const float* __restrict__ v_in,
                    const float* __restrict__ f_in, const float* __restrict__ U_in,
                    const float* __restrict__ W_in, const float* __restrict__ Wf_in,
                    const float* __restrict__ bf_in, const int* __restrict__ steps_ptr,
                    float* __restrict__ out, int Btot)
{
    __shared__ uint4 sWf[8 * 32 * 5];   // gate B-frags [ktg][lane][4 uint4 + pad]
    __shared__ float sBias[64];
    __shared__ float sExA[128 * 12];    // a-partial exchange fp32 (8 used, stride 12)
    __shared__ float sExB[128 * 20];    // fused exchange: a fp32 [0..7] + gate f16x2 [8..15]

    const int tid = threadIdx.x, wid = tid >> 5, lane = tid & 31;
    const int g = lane >> 2, m = lane & 3;
    const int q  = wid & 1;        // row-block (names the pair barrier)
    const int hh = wid >> 1;       // column half
    const int cbase = 32 * hh + 2 * m;
    const int self    = (wid * 32 + lane);
    const int partner = ((wid ^ 2) * 32 + lane);

    // ---- gate B-frag table: Wf [64][128] -> B[n][k], all 8 k-tiles ----
    #pragma unroll
    for (int t = 0; t < 2; t++) {
        int kt = wid + 4 * t;
        #pragma unroll
        for (int j = 0; j < 4; j++) {
            const float* w0 = Wf_in + (8 * (2 * j)     + g) * 128 + 16 * kt;
            const float* w1 = Wf_in + (8 * (2 * j + 1) + g) * 128 + 16 * kt;
            uint4 qq;
            qq.x = bf2(w0[2 * m],     w0[2 * m + 1]);
            qq.y = bf2(w0[8 + 2 * m], w0[9 + 2 * m]);
            qq.z = bf2(w1[2 * m],     w1[2 * m + 1]);
            qq.w = bf2(w1[8 + 2 * m], w1[9 + 2 * m]);
            sWf[(kt * 32 + lane) * 5 + j] = qq;
        }
    }

    // ---- U frags (this warp's K-half): hi AND lo in registers ----
    uint32_t Uh[2][2][2];   // [ktl][nt][pair]
    uint4    Ulr[2];
    #pragma unroll
    for (int ktl = 0; ktl < 2; ktl++) {
        int ktg = 2 * hh + ktl;
        uint32_t lo[2][2];
        #pragma unroll
        for (int nt = 0; nt < 2; nt++) {
            const float* up = U_in + (8 * nt + g) * 64 + 16 * ktg;
            split2(up[2 * m],     up[2 * m + 1], Uh[ktl][nt][0], lo[nt][0]);
            split2(up[8 + 2 * m], up[9 + 2 * m], Uh[ktl][nt][1], lo[nt][1]);
        }
        Ulr[ktl] = make_uint4(lo[0][0], lo[0][1], lo[1][0], lo[1][1]);
    }

    // ---- W frags (this warp's N-half): hi AND lo in registers ----
    uint32_t Wh[4][2];
    uint4    Wlr[2];
    {
        uint32_t wlo[4][2];
        #pragma unroll
        for (int j = 0; j < 4; j++) {
            int n = 8 * (4 * hh + j) + g;
            split2(W_in[(2 * m) * 64 + n],     W_in[(2 * m + 1) * 64 + n], Wh[j][0], wlo[j][0]);
            split2(W_in[(2 * m + 8) * 64 + n], W_in[(2 * m + 9) * 64 + n], Wh[j][1], wlo[j][1]);
        }
        #pragma unroll
        for (int jj = 0; jj < 2; jj++)
            Wlr[jj] = make_uint4(wlo[2 * jj][0], wlo[2 * jj][1], wlo[2 * jj + 1][0], wlo[2 * jj + 1][1]);
    }
    if (tid < 64) sBias[tid] = bf_in[tid];

    __syncthreads();   // one CTA-wide barrier after tables; everything else pair-scoped

    const int steps = steps_ptr[0];
    const int ntiles = Btot / 32;

    float xr[16], vr[16], fr[16], rden[16];
    float aC[2][4];

    // ---- one g1 k-block (this warp's K-half tile ktl) ----
    auto g1_block = [&](int ktl, float aH[2][4], float aL[2][4]){
        uint32_t ah0, ah1, ah2, ah3, al0, al1, al2, al3;
        split2(vr[4 * ktl],      vr[4 * ktl + 1], ah0, al0);
        split2(vr[8 + 4 * ktl],  vr[9 + 4 * ktl], ah1, al1);
        split2(vr[4 * ktl + 2],  vr[4 * ktl + 3], ah2, al2);
        split2(vr[10 + 4 * ktl], vr[11 + 4 * ktl], ah3, al3);
        uint4 ql = Ulr[ktl];
        mma(aH[0], ah0, ah1, ah2, ah3, Uh[ktl][0][0], Uh[ktl][0][1]);
        mma(aH[1], ah0, ah1, ah2, ah3, Uh[ktl][1][0], Uh[ktl][1][1]);
        mma(aL[0], ah0, ah1, ah2, ah3, ql.x, ql.y);
        mma(aL[1], ah0, ah1, ah2, ah3, ql.z, ql.w);
        mma(aL[0], al0, al1, al2, al3, Uh[ktl][0][0], Uh[ktl][0][1]);
        mma(aL[1], al0, al1, al2, al3, Uh[ktl][1][0], Uh[ktl][1][1]);
    };

    // ---- standalone g1 partial + pair exchange through sExA ----
    auto g1_reduce = [&](){
        float aH[2][4], aL[2][4];
        #pragma unroll
        for (int nt = 0; nt < 2; nt++)
            #pragma unroll
            for (int k = 0; k < 4; k++) { aH[nt][k] = 0.f; aL[nt][k] = 0.f; }
        g1_block(0, aH, aL);
        g1_block(1, aH, aL);
        #pragma unroll
        for (int nt = 0; nt < 2; nt++) {
            float4 p = make_float4(aH[nt][0] + aL[nt][0], aH[nt][1] + aL[nt][1],
                                   aH[nt][2] + aL[nt][2], aH[nt][3] + aL[nt][3]);
            *(float4*)&sExA[self * 12 + 4 * nt] = p;
            aC[nt][0] = p.x; aC[nt][1] = p.y; aC[nt][2] = p.z; aC[nt][3] = p.w;
        }
        pairbar(q);
        #pragma unroll
        for (int nt = 0; nt < 2; nt++) {
            float4 p = *(const float4*)&sExA[partner * 12 + 4 * nt];
            aC[nt][0] += p.x; aC[nt][1] += p.y; aC[nt][2] += p.z; aC[nt][3] += p.w;
        }
    };

    // ---- fused: gate partial (+ optional g1), f16x2-packed gate exchange ----
    auto fused_gate = [&](bool with_g1){
        float gc[8][4];
        #pragma unroll
        for (int nt = 0; nt < 8; nt++)
            #pragma unroll
            for (int k = 0; k < 4; k++) gc[nt][k] = 0.0f;
        float aH[2][4], aL[2][4];
        if (with_g1) {
            #pragma unroll
            for (int nt = 0; nt < 2; nt++)
                #pragma unroll
                for (int k = 0; k < 4; k++) { aH[nt][k] = 0.f; aL[nt][k] = 0.f; }
        }
        #pragma unroll
        for (int ktl = 0; ktl < 2; ktl++) {
            float s0, c0, s1, c1;
            uint32_t a0, a1, a2, a3, c0p, c1p, c2p, c3p;
            __sincosf(xr[4 * ktl],      &s0, &c0);
            __sincosf(xr[4 * ktl + 1],  &s1, &c1);
            a0 = bf2(s0, s1); c0p = bf2(c0, c1);
            __sincosf(xr[8 + 4 * ktl],  &s0, &c0);
            __sincosf(xr[9 + 4 * ktl],  &s1, &c1);
            a1 = bf2(s0, s1); c1p = bf2(c0, c1);
            __sincosf(xr[4 * ktl + 2],  &s0, &c0);
            __sincosf(xr[4 * ktl + 3],  &s1, &c1);
            a2 = bf2(s0, s1); c2p = bf2(c0, c1);
            __sincosf(xr[10 + 4 * ktl], &s0, &c0);
            __sincosf(xr[11 + 4 * ktl], &s1, &c1);
            a3 = bf2(s0, s1); c3p = bf2(c0, c1);
            int ktgS = 2 * hh + ktl;       // sin k-tile
            int ktgC = 4 + 2 * hh + ktl;   // cos k-tile
            #pragma unroll
            for (int j = 0; j < 4; j++) {
                uint4 qs = sWf[(ktgS * 32 + lane) * 5 + j];
                mma(gc[2 * j],     a0, a1, a2, a3, qs.x, qs.y);
                mma(gc[2 * j + 1], a0, a1, a2, a3, qs.z, qs.w);
                uint4 qc = sWf[(ktgC * 32 + lane) * 5 + j];
                mma(gc[2 * j],     c0p, c1p, c2p, c3p, qc.x, qc.y);
                mma(gc[2 * j + 1], c0p, c1p, c2p, c3p, qc.z, qc.w);
            }
            if (with_g1) g1_block(ktl, aH, aL);
        }
        // exchange: a-partial fp32 [0..7] + other-half gate partial f16x2 [8..15]
        if (with_g1) {
            #pragma unroll
            for (int nt = 0; nt < 2; nt++) {
                float4 p = make_float4(aH[nt][0] + aL[nt][0], aH[nt][1] + aL[nt][1],
                                       aH[nt][2] + aL[nt][2], aH[nt][3] + aL[nt][3]);
                *(float4*)&sExB[self * 20 + 4 * nt] = p;
                aC[nt][0] = p.x; aC[nt][1] = p.y; aC[nt][2] = p.z; aC[nt][3] = p.w;
            }
        }
        const int oh = 1 - hh;
        {
            uint4 q0, q1;
            q0.x = pkh(gc[4 * oh + 0][0], gc[4 * oh + 0][1]);
            q0.y = pkh(gc[4 * oh + 0][2], gc[4 * oh + 0][3]);
            q0.z = pkh(gc[4 * oh + 1][0], gc[4 * oh + 1][1]);
            q0.w = pkh(gc[4 * oh + 1][2], gc[4 * oh + 1][3]);
            q1.x = pkh(gc[4 * oh + 2][0], gc[4 * oh + 2][1]);
            q1.y = pkh(gc[4 * oh + 2][2], gc[4 * oh + 2][3]);
            q1.z = pkh(gc[4 * oh + 3][0], gc[4 * oh + 3][1]);
            q1.w = pkh(gc[4 * oh + 3][2], gc[4 * oh + 3][3]);
            *(uint4*)&sExB[self * 20 + 8]  = q0;
            *(uint4*)&sExB[self * 20 + 12] = q1;
        }
        pairbar(q);
        if (with_g1) {
            #pragma unroll
            for (int nt = 0; nt < 2; nt++) {
                float4 p = *(const float4*)&sExB[partner * 20 + 4 * nt];
                aC[nt][0] += p.x; aC[nt][1] += p.y; aC[nt][2] += p.z; aC[nt][3] += p.w;
            }
        }
        {
            uint4 q0 = *(const uint4*)&sExB[partner * 20 + 8];
            uint4 q1 = *(const uint4*)&sExB[partner * 20 + 12];
            uint32_t pk[8] = {q0.x, q0.y, q0.z, q0.w, q1.x, q1.y, q1.z, q1.w};
            #pragma unroll
            for (int j = 0; j < 4; j++) {
                float2 pA = h2f2(pk[2 * j]);
                float2 pB = h2f2(pk[2 * j + 1]);
                float g0  = gc[4 * hh + j][0] + pA.x;
                float g1v = gc[4 * hh + j][1] + pA.y;
                float g2v = gc[4 * hh + j][2] + pB.x;
                float g3  = gc[4 * hh + j][3] + pB.y;
                float2 bb = *(const float2*)(sBias + 32 * hh + 8 * j + 2 * m);
                rden[2 * j]     = rdenf(g0 + bb.x);
                rden[2 * j + 1] = rdenf(g1v + bb.y);
                rden[8 + 2 * j] = rdenf(g2v + bb.x);
                rden[9 + 2 * j] = rdenf(g3 + bb.y);
            }
        }
    };

    // ---- g2 fused with state update, 2-way parallel accumulators ----
    auto g2half = [&](bool first){
        uint32_t h0, h1, h2, h3, l0, l1, l2, l3;
        split2(aC[0][0] * aC[0][0], aC[0][1] * aC[0][1], h0, l0);
        split2(aC[0][2] * aC[0][2], aC[0][3] * aC[0][3], h1, l1);
        split2(aC[1][0] * aC[1][0], aC[1][1] * aC[1][1], h2, l2);
        split2(aC[1][2] * aC[1][2], aC[1][3] * aC[1][3], h3, l3);
        #pragma unroll
        for (int jj = 0; jj < 2; jj++) {
            uint4 ql = Wlr[jj];
            uint32_t Wlf[2][2] = {{ql.x, ql.y}, {ql.z, ql.w}};
            #pragma unroll
            for (int u = 0; u < 2; u++) {
                int j = 2 * jj + u;
                float gA[4] = {0.f, 0.f, 0.f, 0.f};
                float gB[4] = {0.f, 0.f, 0.f, 0.f};
                mma(gA, h0, h1, h2, h3, Wh[j][0], Wh[j][1]);
                mma(gB, h0, h1, h2, h3, Wlf[u][0], Wlf[u][1]);
                mma(gA, l0, l1, l2, l3, Wh[j][0], Wh[j][1]);
                #pragma unroll
                for (int k = 0; k < 4; k++) {
                    int i = (k >> 1) * 8 + 2 * j + (k & 1);
                    float gm = gA[k] + gB[k];
                    float vn = (vr[i] + HSTEP * (fr[i] - gm)) * rden[i];
                    vr[i] = vn;
                    if (first) xr[i] = fmaf(DT_EFF, vn, xr[i]);
                }
            }
        }
    };

    // ==================== persistent tile loop ====================
    for (int tile = blockIdx.x; tile < ntiles; tile += NBLK) {
        const int r0 = tile * 32 + q * 16 + g;

        // ---- state into registers ----
        #pragma unroll
        for (int rr = 0; rr < 2; rr++) {
            const size_t base = (size_t)(r0 + 8 * rr) * 64 + cbase;
            #pragma unroll
            for (int t = 0; t < 4; t++) {
                float2 tt;
                tt = *(const float2*)(x_in + base + 8 * t); xr[rr * 8 + 2 * t] = tt.x; xr[rr * 8 + 2 * t + 1] = tt.y;
                tt = *(const float2*)(v_in + base + 8 * t); vr[rr * 8 + 2 * t] = tt.x; vr[rr * 8 + 2 * t + 1] = tt.y;
                tt = *(const float2*)(f_in + base + 8 * t); fr[rr * 8 + 2 * t] = tt.x; fr[rr * 8 + 2 * t + 1] = tt.y;
            }
        }

        // ---- initial friction at x0 ----
        fused_gate(false);

        // ---- main loop (pair barriers only) ----
        for (int s = 0; s < steps; s++) {
            g1_reduce();               // a(v), reduced across K-halves
            g2half(true);              // v_half, x update (rden = mu at old x)
            fused_gate(true);          // mu(x_new) + a(v_half), reduced
            g2half(false);             // final v
        }

        // ---- output: wrap x, write x then v ----
        #pragma unroll
        for (int rr = 0; rr < 2; rr++) {
            const size_t base = (size_t)(r0 + 8 * rr) * 64 + cbase;
            #pragma unroll
            for (int t = 0; t < 4; t++) {
                float X0 = xr[rr * 8 + 2 * t], X1 = xr[rr * 8 + 2 * t + 1];
                float2 qx;
                qx.x = fmaf(-TWO_PI, rintf(X0 * INV_TWO_PI), X0);
                qx.y = fmaf(-TWO_PI, rintf(X1 * INV_TWO_PI), X1);
                *(float2*)(out + base + 8 * t) = qx;
                float2 qv = make_float2(vr[rr * 8 + 2 * t], vr[rr * 8 + 2 * t + 1]);
                *(float2*)(out + (size_t)Btot * 64 + base + 8 * t) = qv;
            }
        }
    }
}

extern "C" void kernel_launch(void* const* d_in, const int* in_sizes, int n_in,
                              void* d_out, int out_size)
{
    const float* x  = (const float*)d_in[0];
    const float* v  = (const float*)d_in[1];
    const float* f  = (const float*)d_in[2];
    const float* U  = (const float*)d_in[3];
    const float* W  = (const float*)d_in[4];
    const float* Wf = (const float*)d_in[5];
    const float* bf = (const float*)d_in[6];
    const int* steps = (const int*)d_in[7];

    float* out = (float*)d_out;
    const int Btot = in_sizes[0] / 64;     // 262144
    const int ntiles = Btot / 32;          // 8192
    const int blocks = (ntiles < NBLK) ? ntiles : NBLK;   // persistent: one wave

    leapfrog_r15_kernel<<<blocks, THREADS>>>(x, v, f, U, W, Wf, bf, steps, out, Btot);
}